// round 2
// baseline (speedup 1.0000x reference)
#include <cuda_runtime.h>
#include <stdint.h>

#define BB 2
#define CC 32
#define HH 64
#define WW 64
#define PP 4096
#define FF 288
#define KK 32
#define NBB 32
#define HIDD 64
#define COUTT 64

// ---------------- device scratch (static, no allocation) ----------------
__device__ float    g_patches[BB*PP*FF];   // 9.4 MB
__device__ float    g_obs[BB*PP*CC];       // 1.0 MB
__device__ uint32_t g_skeys[BB*2*PP];
__device__ int      g_permA[BB*PP];
__device__ int      g_permB[BB*PP];
__device__ float    g_centers[BB*KK*CC];
__device__ float    g_sums[BB*KK*CC];
__device__ float    g_counts[BB*KK];
__device__ int      g_assign[BB*PP];
__device__ int      g_iter[BB];
__device__ int      g_active[BB];
__device__ float    g_sumsF[BB*KK*FF];
__device__ float    g_countsF[BB*KK];
__device__ float    g_attn[BB*KK*NBB];
__device__ float    g_biasv[BB*KK*COUTT];
__device__ float    g_wk[BB*KK*FF*COUTT];  // 4.7 MB

// ---------------- Threefry-2x32 (JAX-compatible core) ----------------
__host__ __device__ inline void threefry2x32(uint32_t k0, uint32_t k1,
                                             uint32_t x0, uint32_t x1,
                                             uint32_t &o0, uint32_t &o1) {
    uint32_t ks2 = k0 ^ k1 ^ 0x1BD11BDAu;
    uint32_t v0 = x0 + k0, v1 = x1 + k1;
#define TF_R(r) { v0 += v1; v1 = (v1 << (r)) | (v1 >> (32 - (r))); v1 ^= v0; }
    TF_R(13) TF_R(15) TF_R(26) TF_R(6)   v0 += k1;  v1 += ks2 + 1u;
    TF_R(17) TF_R(29) TF_R(16) TF_R(24)  v0 += ks2; v1 += k0  + 2u;
    TF_R(13) TF_R(15) TF_R(26) TF_R(6)   v0 += k0;  v1 += k1  + 3u;
    TF_R(17) TF_R(29) TF_R(16) TF_R(24)  v0 += k1;  v1 += ks2 + 4u;
    TF_R(13) TF_R(15) TF_R(26) TF_R(6)   v0 += ks2; v1 += k0  + 5u;
#undef TF_R
    o0 = v0; o1 = v1;
}

// ---------------- init: zero accumulators, reset loop state ----------------
__global__ void k_init() {
    int t = blockIdx.x * blockDim.x + threadIdx.x;
    if (t < BB*KK*FF) g_sumsF[t] = 0.f;
    if (t < BB*KK*CC) g_sums[t] = 0.f;
    if (t < BB*KK) { g_counts[t] = 0.f; g_countsF[t] = 0.f; }
    if (t < BB) { g_iter[t] = 0; g_active[t] = 1; }
}

// ---------------- unfold3 + channel-mean features ----------------
__global__ void k_prep(const float* __restrict__ x) {
    int warp = threadIdx.x >> 5, lane = threadIdx.x & 31;
    int gp = blockIdx.x * 4 + warp;           // 0..8191 = b*4096+p
    int b = gp >> 12, p = gp & 4095;
    int py = p >> 6, px = p & 63;
    const float* xc = x + (size_t)(b*CC + lane) * HH * WW;
    float* prow = g_patches + (size_t)gp * FF + lane * 9;
    float s = 0.f;
#pragma unroll
    for (int i = 0; i < 3; i++) {
        int yy = py + i - 1;
#pragma unroll
        for (int j = 0; j < 3; j++) {
            int xx = px + j - 1;
            float v = (yy >= 0 && yy < HH && xx >= 0 && xx < WW) ? xc[yy*WW + xx] : 0.f;
            prow[i*3 + j] = v;
            s += v;
        }
    }
    g_obs[(size_t)gp * CC + lane] = s / 9.f;
}

// ---------------- sort keys for permutation (partitionable threefry) ----------
__global__ void k_keys(uint4 s0, uint4 s1) {
    int t = blockIdx.x * blockDim.x + threadIdx.x;  // [b][round][i]
    if (t >= BB*2*PP) return;
    int b = t >> 13, r = (t >> 12) & 1, i = t & 4095;
    uint4 s = b ? s1 : s0;
    uint32_t k0 = r ? s.z : s.x;
    uint32_t k1 = r ? s.w : s.y;
    uint32_t o0, o1;
    threefry2x32(k0, k1, 0u, (uint32_t)i, o0, o1);
    g_skeys[t] = o0 ^ o1;   // xor-fold (32-bit random_bits, partitionable mode)
}

// ---------------- stable sort via exact rank (O(n^2), deterministic) --------
__global__ void k_rank(int round) {
    int b = blockIdx.x >> 5;
    int base = (blockIdx.x & 31) << 7;
    __shared__ uint32_t sk[PP];
    const uint32_t* kp = g_skeys + ((b*2 + round) << 12);
    for (int i = threadIdx.x; i < PP; i += blockDim.x) sk[i] = kp[i];
    __syncthreads();
    int i = base + threadIdx.x;
    uint32_t myk = sk[i];
    int rank = 0;
    for (int j = 0; j < PP; j++) {
        uint32_t kj = sk[j];
        rank += (kj < myk) || (kj == myk && j < i);
    }
    if (round == 0) g_permA[b*PP + rank] = i;
    else            g_permB[b*PP + rank] = g_permA[b*PP + i];
}

__global__ void k_initc() {
    int b = blockIdx.x, t = threadIdx.x;        // 1024 threads = 32k x 32d
    int k = t >> 5, d = t & 31;
    g_centers[b*KK*CC + t] = g_obs[(size_t)(b*PP + g_permB[b*PP + k])*CC + d];
}

// ---------------- kmeans assign (+accumulate) ----------------
__global__ void k_assign(int finalPass, float* idx_out) {
    int b = blockIdx.x >> 5;
    int pbase = (blockIdx.x & 31) << 7;
    if (!finalPass && !g_active[b]) return;
    __shared__ float sc[KK*CC];
    __shared__ float scn[KK];
    __shared__ float ssum[KK*CC];
    __shared__ float scnt[KK];
    int t = threadIdx.x;   // 128
    for (int i = t; i < KK*CC; i += 128) { sc[i] = g_centers[b*KK*CC + i]; ssum[i] = 0.f; }
    if (t < KK) scnt[t] = 0.f;
    __syncthreads();
    if (t < KK) {
        float q = 0.f;
#pragma unroll
        for (int d = 0; d < CC; d++) { float c = sc[t*CC + d]; q += c*c; }
        scn[t] = q;
    }
    __syncthreads();
    int p = pbase + t;
    const float* op = g_obs + (size_t)(b*PP + p) * CC;
    float s[CC]; float sn = 0.f;
#pragma unroll
    for (int d = 0; d < CC; d++) { s[d] = op[d]; sn += s[d]*s[d]; }
    float best = 3.4028235e38f; int bi = 0;
    for (int k = 0; k < KK; k++) {
        float dot = 0.f;
#pragma unroll
        for (int d = 0; d < CC; d++) dot += s[d]*sc[k*CC + d];
        float d2 = sn - 2.0f*dot + scn[k];
        if (d2 < best) { best = d2; bi = k; }
    }
    g_assign[b*PP + p] = bi;
    if (finalPass) {
        if (idx_out) idx_out[b*PP + p] = (float)bi;
    } else {
        atomicAdd(&scnt[bi], 1.f);
#pragma unroll
        for (int d = 0; d < CC; d++) atomicAdd(&ssum[bi*CC + d], s[d]);
        __syncthreads();
        for (int i = t; i < KK*CC; i += 128) atomicAdd(&g_sums[b*KK*CC + i], ssum[i]);
        if (t < KK) atomicAdd(&g_counts[b*KK + t], scnt[t]);
    }
}

// ---------------- kmeans center update + convergence flag ----------------
__global__ void k_fin() {
    int b = blockIdx.x;
    if (!g_active[b]) return;
    int t = threadIdx.x;                 // 1024
    int k = t >> 5, d = t & 31;
    float oldc = g_centers[b*KK*CC + t];
    float cnt  = g_counts[b*KK + k];
    float sm   = g_sums[b*KK*CC + t];
    float nv = (cnt > 0.f) ? (sm / fmaxf(cnt, 1.f)) : oldc;
    float diff = nv - oldc;
    float q = diff*diff;
#pragma unroll
    for (int off = 16; off > 0; off >>= 1) q += __shfl_down_sync(0xffffffffu, q, off);
    __shared__ float wn[KK];
    if (d == 0) wn[k] = sqrtf(q);
    __syncthreads();
    if (t == 0) {
        float sh = 0.f;
        for (int kk = 0; kk < KK; kk++) sh += wn[kk];
        int it = g_iter[b] + 1;
        g_iter[b] = it;
        g_active[b] = (it < 20 && sh >= 20.48f) ? 1 : 0;   // TOL*n = 0.005*4096
    }
    g_centers[b*KK*CC + t] = nv;
    g_sums[b*KK*CC + t] = 0.f;
    if (d == 0) g_counts[b*KK + k] = 0.f;
}

// ---------------- per-cluster 288-dim centroid accumulation --------------
__global__ void k_sumsF() {
    int t = blockIdx.x * blockDim.x + threadIdx.x;
    if (t >= BB*PP*FF) return;
    int f = t % FF;
    int bp = t / FF;
    int b = bp >> 12;
    int k = g_assign[bp];
    atomicAdd(&g_sumsF[(size_t)(b*KK + k)*FF + f], g_patches[t]);
}

__global__ void k_cntF() {
    int t = blockIdx.x * blockDim.x + threadIdx.x;
    if (t >= BB*PP) return;
    atomicAdd(&g_countsF[(t >> 12)*KK + g_assign[t]], 1.f);
}

// ---------------- the two tiny MLPs + softmax ----------------
__global__ void k_mlp(const float* kw1, const float* kb1, const float* kw2, const float* kb2,
                      const float* kw3, const float* kb3,
                      const float* bw1, const float* bb1, const float* bw2, const float* bb2,
                      const float* bw3, const float* bb3) {
    int b = blockIdx.x >> 5, k = blockIdx.x & 31;
    int t = threadIdx.x;   // 64
    __shared__ float cen[FF];
    __shared__ float h1[HIDD];
    __shared__ float h2[HIDD];
    float cnt = g_countsF[b*KK + k];
    float dv = fmaxf(cnt, 1.f);
    for (int f = t; f < FF; f += 64) cen[f] = g_sumsF[(size_t)(b*KK + k)*FF + f] / dv;
    __syncthreads();
    float a = kb1[t];
    for (int f = 0; f < FF; f++) a += cen[f]*kw1[f*HIDD + t];
    h1[t] = fmaxf(a, 0.f);
    __syncthreads();
    a = kb2[t];
#pragma unroll
    for (int i = 0; i < HIDD; i++) a += h1[i]*kw2[i*HIDD + t];
    h2[t] = fmaxf(a, 0.f);
    __syncthreads();
    if (t < NBB) {
        a = kb3[t];
#pragma unroll
        for (int i = 0; i < HIDD; i++) a += h2[i]*kw3[i*NBB + t];
        float m = a;
#pragma unroll
        for (int off = 16; off > 0; off >>= 1) m = fmaxf(m, __shfl_xor_sync(0xffffffffu, m, off));
        float e = expf(a - m);
        float ss = e;
#pragma unroll
        for (int off = 16; off > 0; off >>= 1) ss += __shfl_xor_sync(0xffffffffu, ss, off);
        g_attn[(b*KK + k)*NBB + t] = e / ss;
    }
    __syncthreads();
    a = bb1[t];
    for (int f = 0; f < FF; f++) a += cen[f]*bw1[f*HIDD + t];
    h1[t] = fmaxf(a, 0.f);
    __syncthreads();
    a = bb2[t];
#pragma unroll
    for (int i = 0; i < HIDD; i++) a += h1[i]*bw2[i*HIDD + t];
    h2[t] = fmaxf(a, 0.f);
    __syncthreads();
    a = bb3[t];
#pragma unroll
    for (int i = 0; i < HIDD; i++) a += h2[i]*bw3[i*COUTT + t];
    g_biasv[(b*KK + k)*COUTT + t] = a;
}

// ---------------- kernels = attn @ base_kernels ----------------
__global__ void k_wk(const float* __restrict__ base) {
    int col0 = blockIdx.x * 128;     // column in flattened (f*64+c) space
    int t = threadIdx.x;             // 128
    __shared__ float bt[NBB*128];
    __shared__ float at[BB*KK*NBB];  // 2048
#pragma unroll
    for (int n = 0; n < NBB; n++) bt[n*128 + t] = base[(size_t)n*(FF*COUTT) + col0 + t];
    for (int i = t; i < BB*KK*NBB; i += 128) at[i] = g_attn[i];
    __syncthreads();
    for (int row = 0; row < BB*KK; row++) {
        float acc = 0.f;
#pragma unroll
        for (int n = 0; n < NBB; n++) acc += at[row*NBB + n]*bt[n*128 + t];
        g_wk[(size_t)row*(FF*COUTT) + col0 + t] = acc;
    }
}

// ---------------- final grouped conv: out[b,c,p] ----------------
__global__ void k_conv(float* __restrict__ out) {
    int gp0 = blockIdx.x * 4;
    int t = threadIdx.x;   // 256 = 4 pixels x 64 cout
    __shared__ float pat[4*FF];
    for (int i = t; i < 4*FF; i += 256) pat[i] = g_patches[(size_t)gp0*FF + i];
    __syncthreads();
    int lp = t >> 6, c = t & 63;
    int gp = gp0 + lp;
    int b = gp >> 12, p = gp & 4095;
    int k = g_assign[gp];
    const float* w = g_wk + (size_t)(b*KK + k)*(FF*COUTT) + c;
    const float* pr = pat + lp*FF;
    float acc = 0.f;
#pragma unroll 8
    for (int f = 0; f < FF; f++) acc += pr[f]*w[(size_t)f*COUTT];
    acc += g_biasv[(b*KK + k)*COUTT + c];
    out[(size_t)(b*COUTT + c)*PP + p] = acc;
}

// ---------------- launch ----------------
extern "C" void kernel_launch(void* const* d_in, const int* in_sizes, int n_in,
                              void* d_out, int out_size) {
    const float* x    = (const float*)d_in[0];
    const float* base = (const float*)d_in[1];
    const float* kw1 = (const float*)d_in[2];  const float* kb1 = (const float*)d_in[3];
    const float* kw2 = (const float*)d_in[4];  const float* kb2 = (const float*)d_in[5];
    const float* kw3 = (const float*)d_in[6];  const float* kb3 = (const float*)d_in[7];
    const float* bw1 = (const float*)d_in[8];  const float* bb1 = (const float*)d_in[9];
    const float* bw2 = (const float*)d_in[10]; const float* bb2 = (const float*)d_in[11];
    const float* bw3 = (const float*)d_in[12]; const float* bb3 = (const float*)d_in[13];
    float* out = (float*)d_out;

    // JAX key chain (partitionable/fold-like split): key(42) = (0,42)
    uint32_t bk0x, bk0y, bk1x, bk1y;
    threefry2x32(0u, 42u, 0u, 0u, bk0x, bk0y);   // batch 0 key
    threefry2x32(0u, 42u, 0u, 1u, bk1x, bk1y);   // batch 1 key
    uint4 s0, s1;
    {
        uint32_t c0, c1, u, v;
        threefry2x32(bk0x, bk0y, 0u, 1u, u, v); s0.x = u; s0.y = v;   // b0 round-1 subkey
        threefry2x32(bk0x, bk0y, 0u, 0u, c0, c1);                      // b0 carried key
        threefry2x32(c0, c1, 0u, 1u, u, v);     s0.z = u; s0.w = v;   // b0 round-2 subkey
        threefry2x32(bk1x, bk1y, 0u, 1u, u, v); s1.x = u; s1.y = v;
        threefry2x32(bk1x, bk1y, 0u, 0u, c0, c1);
        threefry2x32(c0, c1, 0u, 1u, u, v);     s1.z = u; s1.w = v;
    }

    float* idx_out = (out_size >= BB*COUTT*PP + BB*PP) ? (out + BB*COUTT*PP) : nullptr;

    k_init<<<72, 256>>>();
    k_prep<<<2048, 128>>>(x);
    k_keys<<<16, 1024>>>(s0, s1);
    k_rank<<<64, 128>>>(0);
    k_rank<<<64, 128>>>(1);
    k_initc<<<2, 1024>>>();
    for (int it = 0; it < 20; it++) {
        k_assign<<<64, 128>>>(0, nullptr);
        k_fin<<<2, 1024>>>();
    }
    k_assign<<<64, 128>>>(1, idx_out);
    k_sumsF<<<9216, 256>>>();
    k_cntF<<<8, 1024>>>();
    k_mlp<<<64, 64>>>(kw1, kb1, kw2, kb2, kw3, kb3, bw1, bb1, bw2, bb2, bw3, bb3);
    k_wk<<<144, 128>>>(base);
    k_conv<<<2048, 256>>>(out);
}

// round 3
// speedup vs baseline: 1.0028x; 1.0028x over previous
#include <cuda_runtime.h>
#include <stdint.h>

#define BB 2
#define CC 32
#define HH 64
#define WW 64
#define PP 4096
#define FF 288
#define KK 32
#define NBB 32
#define HIDD 64
#define COUTT 64

// ---------------- device scratch (static, no allocation) ----------------
__device__ float    g_patches[BB*PP*FF];   // 9.4 MB
__device__ float    g_obs[BB*PP*CC];       // 1.0 MB
__device__ uint32_t g_skeys[BB*2*PP];
__device__ int      g_permA[BB*PP];
__device__ int      g_permB[BB*PP];
__device__ float    g_centers[BB*KK*CC];
__device__ float    g_sums[BB*KK*CC];
__device__ float    g_counts[BB*KK];
__device__ int      g_assign[BB*PP];
__device__ int      g_iter[BB];
__device__ int      g_active[BB];
__device__ float    g_sumsF[BB*KK*FF];
__device__ float    g_countsF[BB*KK];
__device__ float    g_attn[BB*KK*NBB];
__device__ float    g_biasv[BB*KK*COUTT];
__device__ float    g_wk[BB*KK*FF*COUTT];  // 4.7 MB

// ---------------- Threefry-2x32 (JAX-compatible core) ----------------
__host__ __device__ inline void threefry2x32(uint32_t k0, uint32_t k1,
                                             uint32_t x0, uint32_t x1,
                                             uint32_t &o0, uint32_t &o1) {
    uint32_t ks2 = k0 ^ k1 ^ 0x1BD11BDAu;
    uint32_t v0 = x0 + k0, v1 = x1 + k1;
#define TF_R(r) { v0 += v1; v1 = (v1 << (r)) | (v1 >> (32 - (r))); v1 ^= v0; }
    TF_R(13) TF_R(15) TF_R(26) TF_R(6)   v0 += k1;  v1 += ks2 + 1u;
    TF_R(17) TF_R(29) TF_R(16) TF_R(24)  v0 += ks2; v1 += k0  + 2u;
    TF_R(13) TF_R(15) TF_R(26) TF_R(6)   v0 += k0;  v1 += k1  + 3u;
    TF_R(17) TF_R(29) TF_R(16) TF_R(24)  v0 += k1;  v1 += ks2 + 4u;
    TF_R(13) TF_R(15) TF_R(26) TF_R(6)   v0 += ks2; v1 += k0  + 5u;
#undef TF_R
    o0 = v0; o1 = v1;
}

// ---------------- init: zero accumulators, reset loop state ----------------
__global__ void k_init() {
    int t = blockIdx.x * blockDim.x + threadIdx.x;
    if (t < BB*KK*FF) g_sumsF[t] = 0.f;
    if (t < BB*KK*CC) g_sums[t] = 0.f;
    if (t < BB*KK) { g_counts[t] = 0.f; g_countsF[t] = 0.f; }
    if (t < BB) { g_iter[t] = 0; g_active[t] = 1; }
}

// ---------------- unfold3 + channel-mean features ----------------
__global__ void k_prep(const float* __restrict__ x) {
    int warp = threadIdx.x >> 5, lane = threadIdx.x & 31;
    int gp = blockIdx.x * 4 + warp;           // 0..8191 = b*4096+p
    int b = gp >> 12, p = gp & 4095;
    int py = p >> 6, px = p & 63;
    const float* xc = x + (size_t)(b*CC + lane) * HH * WW;
    float* prow = g_patches + (size_t)gp * FF + lane * 9;
    float s = 0.f;
#pragma unroll
    for (int i = 0; i < 3; i++) {
        int yy = py + i - 1;
#pragma unroll
        for (int j = 0; j < 3; j++) {
            int xx = px + j - 1;
            float v = (yy >= 0 && yy < HH && xx >= 0 && xx < WW) ? xc[yy*WW + xx] : 0.f;
            prow[i*3 + j] = v;
            s += v;
        }
    }
    g_obs[(size_t)gp * CC + lane] = s / 9.f;
}

// ---------------- sort keys for permutation (partitionable threefry) ----------
__global__ void k_keys(uint4 s0, uint4 s1) {
    int t = blockIdx.x * blockDim.x + threadIdx.x;  // [b][round][i]
    if (t >= BB*2*PP) return;
    int b = t >> 13, r = (t >> 12) & 1, i = t & 4095;
    uint4 s = b ? s1 : s0;
    uint32_t k0 = r ? s.z : s.x;
    uint32_t k1 = r ? s.w : s.y;
    uint32_t o0, o1;
    threefry2x32(k0, k1, 0u, (uint32_t)i, o0, o1);
    g_skeys[t] = o0 ^ o1;   // xor-fold (32-bit random_bits, partitionable mode)
}

// ---------------- stable sort via exact rank (O(n^2), deterministic) --------
__global__ void k_rank(int round) {
    int b = blockIdx.x >> 5;
    int base = (blockIdx.x & 31) << 7;
    __shared__ uint32_t sk[PP];
    const uint32_t* kp = g_skeys + ((b*2 + round) << 12);
    for (int i = threadIdx.x; i < PP; i += blockDim.x) sk[i] = kp[i];
    __syncthreads();
    int i = base + threadIdx.x;
    uint32_t myk = sk[i];
    int rank = 0;
    for (int j = 0; j < PP; j++) {
        uint32_t kj = sk[j];
        rank += (kj < myk) || (kj == myk && j < i);
    }
    if (round == 0) g_permA[b*PP + rank] = i;
    else            g_permB[b*PP + rank] = g_permA[b*PP + i];
}

__global__ void k_initc() {
    int b = blockIdx.x, t = threadIdx.x;        // 1024 threads = 32k x 32d
    int k = t >> 5, d = t & 31;
    g_centers[b*KK*CC + t] = g_obs[(size_t)(b*PP + g_permB[b*PP + k])*CC + d];
}

// ---------------- kmeans assign (+accumulate) ----------------
__global__ void k_assign(int finalPass, float* idx_out) {
    int b = blockIdx.x >> 5;
    int pbase = (blockIdx.x & 31) << 7;
    if (!finalPass && !g_active[b]) return;
    __shared__ float sc[KK*CC];
    __shared__ float scn[KK];
    __shared__ float ssum[KK*CC];
    __shared__ float scnt[KK];
    int t = threadIdx.x;   // 128
    for (int i = t; i < KK*CC; i += 128) { sc[i] = g_centers[b*KK*CC + i]; ssum[i] = 0.f; }
    if (t < KK) scnt[t] = 0.f;
    __syncthreads();
    if (t < KK) {
        float q = 0.f;
#pragma unroll
        for (int d = 0; d < CC; d++) { float c = sc[t*CC + d]; q += c*c; }
        scn[t] = q;
    }
    __syncthreads();
    int p = pbase + t;
    const float* op = g_obs + (size_t)(b*PP + p) * CC;
    float s[CC]; float sn = 0.f;
#pragma unroll
    for (int d = 0; d < CC; d++) { s[d] = op[d]; sn += s[d]*s[d]; }
    float best = 3.4028235e38f; int bi = 0;
    for (int k = 0; k < KK; k++) {
        float dot = 0.f;
#pragma unroll
        for (int d = 0; d < CC; d++) dot += s[d]*sc[k*CC + d];
        float d2 = sn - 2.0f*dot + scn[k];
        if (d2 < best) { best = d2; bi = k; }
    }
    g_assign[b*PP + p] = bi;
    if (finalPass) {
        if (idx_out) idx_out[b*PP + p] = (float)bi;
    } else {
        atomicAdd(&scnt[bi], 1.f);
#pragma unroll
        for (int d = 0; d < CC; d++) atomicAdd(&ssum[bi*CC + d], s[d]);
        __syncthreads();
        for (int i = t; i < KK*CC; i += 128) atomicAdd(&g_sums[b*KK*CC + i], ssum[i]);
        if (t < KK) atomicAdd(&g_counts[b*KK + t], scnt[t]);
    }
}

// ---------------- kmeans center update + convergence flag ----------------
__global__ void k_fin() {
    int b = blockIdx.x;
    if (!g_active[b]) return;
    int t = threadIdx.x;                 // 1024
    int k = t >> 5, d = t & 31;
    float oldc = g_centers[b*KK*CC + t];
    float cnt  = g_counts[b*KK + k];
    float sm   = g_sums[b*KK*CC + t];
    float nv = (cnt > 0.f) ? (sm / fmaxf(cnt, 1.f)) : oldc;
    float diff = nv - oldc;
    float q = diff*diff;
#pragma unroll
    for (int off = 16; off > 0; off >>= 1) q += __shfl_down_sync(0xffffffffu, q, off);
    __shared__ float wn[KK];
    if (d == 0) wn[k] = sqrtf(q);
    __syncthreads();
    if (t == 0) {
        float sh = 0.f;
        for (int kk = 0; kk < KK; kk++) sh += wn[kk];
        int it = g_iter[b] + 1;
        g_iter[b] = it;
        g_active[b] = (it < 20 && sh >= 20.48f) ? 1 : 0;   // TOL*n = 0.005*4096
    }
    g_centers[b*KK*CC + t] = nv;
    g_sums[b*KK*CC + t] = 0.f;
    if (d == 0) g_counts[b*KK + k] = 0.f;
}

// ---------------- per-cluster 288-dim centroid accumulation --------------
__global__ void k_sumsF() {
    int t = blockIdx.x * blockDim.x + threadIdx.x;
    if (t >= BB*PP*FF) return;
    int f = t % FF;
    int bp = t / FF;
    int b = bp >> 12;
    int k = g_assign[bp];
    atomicAdd(&g_sumsF[(size_t)(b*KK + k)*FF + f], g_patches[t]);
}

__global__ void k_cntF() {
    int t = blockIdx.x * blockDim.x + threadIdx.x;
    if (t >= BB*PP) return;
    atomicAdd(&g_countsF[(t >> 12)*KK + g_assign[t]], 1.f);
}

// ---------------- the two tiny MLPs + softmax ----------------
__global__ void k_mlp(const float* kw1, const float* kb1, const float* kw2, const float* kb2,
                      const float* kw3, const float* kb3,
                      const float* bw1, const float* bb1, const float* bw2, const float* bb2,
                      const float* bw3, const float* bb3) {
    int b = blockIdx.x >> 5, k = blockIdx.x & 31;
    int t = threadIdx.x;   // 64
    __shared__ float cen[FF];
    __shared__ float h1[HIDD];
    __shared__ float h2[HIDD];
    float cnt = g_countsF[b*KK + k];
    float dv = fmaxf(cnt, 1.f);
    for (int f = t; f < FF; f += 64) cen[f] = g_sumsF[(size_t)(b*KK + k)*FF + f] / dv;
    __syncthreads();
    float a = kb1[t];
    for (int f = 0; f < FF; f++) a += cen[f]*kw1[f*HIDD + t];
    h1[t] = fmaxf(a, 0.f);
    __syncthreads();
    a = kb2[t];
#pragma unroll
    for (int i = 0; i < HIDD; i++) a += h1[i]*kw2[i*HIDD + t];
    h2[t] = fmaxf(a, 0.f);
    __syncthreads();
    if (t < NBB) {
        a = kb3[t];
#pragma unroll
        for (int i = 0; i < HIDD; i++) a += h2[i]*kw3[i*NBB + t];
        float m = a;
#pragma unroll
        for (int off = 16; off > 0; off >>= 1) m = fmaxf(m, __shfl_xor_sync(0xffffffffu, m, off));
        float e = expf(a - m);
        float ss = e;
#pragma unroll
        for (int off = 16; off > 0; off >>= 1) ss += __shfl_xor_sync(0xffffffffu, ss, off);
        g_attn[(b*KK + k)*NBB + t] = e / ss;
    }
    __syncthreads();
    a = bb1[t];
    for (int f = 0; f < FF; f++) a += cen[f]*bw1[f*HIDD + t];
    h1[t] = fmaxf(a, 0.f);
    __syncthreads();
    a = bb2[t];
#pragma unroll
    for (int i = 0; i < HIDD; i++) a += h1[i]*bw2[i*HIDD + t];
    h2[t] = fmaxf(a, 0.f);
    __syncthreads();
    a = bb3[t];
#pragma unroll
    for (int i = 0; i < HIDD; i++) a += h2[i]*bw3[i*COUTT + t];
    g_biasv[(b*KK + k)*COUTT + t] = a;
}

// ---------------- kernels = attn @ base_kernels ----------------
__global__ void k_wk(const float* __restrict__ base) {
    int col0 = blockIdx.x * 128;     // column in flattened (f*64+c) space
    int t = threadIdx.x;             // 128
    __shared__ float bt[NBB*128];
    __shared__ float at[BB*KK*NBB];  // 2048
#pragma unroll
    for (int n = 0; n < NBB; n++) bt[n*128 + t] = base[(size_t)n*(FF*COUTT) + col0 + t];
    for (int i = t; i < BB*KK*NBB; i += 128) at[i] = g_attn[i];
    __syncthreads();
    for (int row = 0; row < BB*KK; row++) {
        float acc = 0.f;
#pragma unroll
        for (int n = 0; n < NBB; n++) acc += at[row*NBB + n]*bt[n*128 + t];
        g_wk[(size_t)row*(FF*COUTT) + col0 + t] = acc;
    }
}

// ---------------- final grouped conv: out[b,c,p] ----------------
__global__ void k_conv(float* __restrict__ out) {
    int gp0 = blockIdx.x * 4;
    int t = threadIdx.x;   // 256 = 4 pixels x 64 cout
    __shared__ float pat[4*FF];
    for (int i = t; i < 4*FF; i += 256) pat[i] = g_patches[(size_t)gp0*FF + i];
    __syncthreads();
    int lp = t >> 6, c = t & 63;
    int gp = gp0 + lp;
    int b = gp >> 12, p = gp & 4095;
    int k = g_assign[gp];
    const float* w = g_wk + (size_t)(b*KK + k)*(FF*COUTT) + c;
    const float* pr = pat + lp*FF;
    float acc = 0.f;
#pragma unroll 8
    for (int f = 0; f < FF; f++) acc += pr[f]*w[(size_t)f*COUTT];
    acc += g_biasv[(b*KK + k)*COUTT + c];
    out[(size_t)(b*COUTT + c)*PP + p] = acc;
}

// ---------------- launch ----------------
extern "C" void kernel_launch(void* const* d_in, const int* in_sizes, int n_in,
                              void* d_out, int out_size) {
    const float* x    = (const float*)d_in[0];
    const float* base = (const float*)d_in[1];
    const float* kw1 = (const float*)d_in[2];  const float* kb1 = (const float*)d_in[3];
    const float* kw2 = (const float*)d_in[4];  const float* kb2 = (const float*)d_in[5];
    const float* kw3 = (const float*)d_in[6];  const float* kb3 = (const float*)d_in[7];
    const float* bw1 = (const float*)d_in[8];  const float* bb1 = (const float*)d_in[9];
    const float* bw2 = (const float*)d_in[10]; const float* bb2 = (const float*)d_in[11];
    const float* bw3 = (const float*)d_in[12]; const float* bb3 = (const float*)d_in[13];
    float* out = (float*)d_out;

    // JAX key chain (partitionable/fold-like split): key(42) = (0,42)
    uint32_t bk0x, bk0y, bk1x, bk1y;
    threefry2x32(0u, 42u, 0u, 0u, bk0x, bk0y);   // batch 0 key
    threefry2x32(0u, 42u, 0u, 1u, bk1x, bk1y);   // batch 1 key
    uint4 s0, s1;
    {
        uint32_t c0, c1, u, v;
        threefry2x32(bk0x, bk0y, 0u, 1u, u, v); s0.x = u; s0.y = v;   // b0 round-1 subkey
        threefry2x32(bk0x, bk0y, 0u, 0u, c0, c1);                      // b0 carried key
        threefry2x32(c0, c1, 0u, 1u, u, v);     s0.z = u; s0.w = v;   // b0 round-2 subkey
        threefry2x32(bk1x, bk1y, 0u, 1u, u, v); s1.x = u; s1.y = v;
        threefry2x32(bk1x, bk1y, 0u, 0u, c0, c1);
        threefry2x32(c0, c1, 0u, 1u, u, v);     s1.z = u; s1.w = v;
    }

    float* idx_out = (out_size >= BB*COUTT*PP + BB*PP) ? (out + BB*COUTT*PP) : nullptr;

    k_init<<<72, 256>>>();
    k_prep<<<2048, 128>>>(x);
    k_keys<<<16, 1024>>>(s0, s1);
    k_rank<<<64, 128>>>(0);
    k_rank<<<64, 128>>>(1);
    k_initc<<<2, 1024>>>();
    for (int it = 0; it < 20; it++) {
        k_assign<<<64, 128>>>(0, nullptr);
        k_fin<<<2, 1024>>>();
    }
    k_assign<<<64, 128>>>(1, idx_out);
    k_sumsF<<<9216, 256>>>();
    k_cntF<<<8, 1024>>>();
    k_mlp<<<64, 64>>>(kw1, kb1, kw2, kb2, kw3, kb3, bw1, bb1, bw2, bb2, bw3, bb3);
    k_wk<<<144, 128>>>(base);
    k_conv<<<2048, 256>>>(out);
}

// round 4
// speedup vs baseline: 1.0701x; 1.0671x over previous
#include <cuda_runtime.h>
#include <stdint.h>

#define BB 2
#define CC 32
#define HH 64
#define WW 64
#define PP 4096
#define FF 288
#define KK 32
#define NBB 32
#define HIDD 64
#define COUTT 64

// ---------------- device scratch (static, no allocation) ----------------
__device__ float    g_patches[BB*PP*FF];   // 9.4 MB
__device__ float    g_obs[BB*PP*CC];       // 1.0 MB
__device__ uint32_t g_skeys[BB*2*PP];
__device__ uint32_t g_rank[BB*2*PP];
__device__ int      g_permA[BB*PP];
__device__ int      g_initidx[BB*KK];
__device__ float    g_centers[BB*KK*CC];
__device__ float    g_sums[BB*KK*CC];
__device__ float    g_counts[BB*KK];
__device__ int      g_done[BB];
__device__ int      g_assign[BB*PP];
__device__ int      g_iter[BB];
__device__ int      g_active[BB];
__device__ int      g_cnt[BB*KK];
__device__ int      g_cursor[BB*KK];
__device__ int      g_off[BB*KK + 1];
__device__ int      g_plist[BB*PP];
__device__ int      g_tileBK[224];
__device__ int      g_tileM0[224];
__device__ int      g_ntiles;
__device__ float    g_sumsF[BB*KK*FF];
__device__ float    g_attn[BB*KK*NBB];
__device__ float    g_biasv[BB*KK*COUTT];
__device__ float    g_wk[BB*KK*FF*COUTT];  // 4.7 MB

// ---------------- Threefry-2x32 (JAX-compatible core) ----------------
__host__ __device__ inline void threefry2x32(uint32_t k0, uint32_t k1,
                                             uint32_t x0, uint32_t x1,
                                             uint32_t &o0, uint32_t &o1) {
    uint32_t ks2 = k0 ^ k1 ^ 0x1BD11BDAu;
    uint32_t v0 = x0 + k0, v1 = x1 + k1;
#define TF_R(r) { v0 += v1; v1 = (v1 << (r)) | (v1 >> (32 - (r))); v1 ^= v0; }
    TF_R(13) TF_R(15) TF_R(26) TF_R(6)   v0 += k1;  v1 += ks2 + 1u;
    TF_R(17) TF_R(29) TF_R(16) TF_R(24)  v0 += ks2; v1 += k0  + 2u;
    TF_R(13) TF_R(15) TF_R(26) TF_R(6)   v0 += k0;  v1 += k1  + 3u;
    TF_R(17) TF_R(29) TF_R(16) TF_R(24)  v0 += k1;  v1 += ks2 + 4u;
    TF_R(13) TF_R(15) TF_R(26) TF_R(6)   v0 += ks2; v1 += k0  + 5u;
#undef TF_R
    o0 = v0; o1 = v1;
}

// ---------------- init: zero accumulators, reset loop state ----------------
__global__ void k_init() {
    int t = blockIdx.x * blockDim.x + threadIdx.x;
    if (t < BB*KK*FF) g_sumsF[t] = 0.f;
    if (t < BB*KK*CC) g_sums[t] = 0.f;
    if (t < BB*KK) { g_counts[t] = 0.f; g_cnt[t] = 0; g_cursor[t] = 0; }
    if (t < BB) { g_iter[t] = 0; g_active[t] = 1; g_done[t] = 0; }
}

// ---------------- unfold3 + channel-mean features ----------------
__global__ void k_prep(const float* __restrict__ x) {
    int warp = threadIdx.x >> 5, lane = threadIdx.x & 31;
    int gp = blockIdx.x * 4 + warp;           // 0..8191 = b*4096+p
    int b = gp >> 12, p = gp & 4095;
    int py = p >> 6, px = p & 63;
    const float* xc = x + (size_t)(b*CC + lane) * HH * WW;
    float* prow = g_patches + (size_t)gp * FF + lane * 9;
    float s = 0.f;
#pragma unroll
    for (int i = 0; i < 3; i++) {
        int yy = py + i - 1;
#pragma unroll
        for (int j = 0; j < 3; j++) {
            int xx = px + j - 1;
            float v = (yy >= 0 && yy < HH && xx >= 0 && xx < WW) ? xc[yy*WW + xx] : 0.f;
            prow[i*3 + j] = v;
            s += v;
        }
    }
    g_obs[(size_t)gp * CC + lane] = s / 9.f;
}

// ---------------- sort keys for permutation (partitionable threefry) ----------
__global__ void k_keys(uint4 s0, uint4 s1) {
    int t = blockIdx.x * blockDim.x + threadIdx.x;  // [b][round][i]
    if (t >= BB*2*PP) return;
    int b = t >> 13, r = (t >> 12) & 1, i = t & 4095;
    uint4 s = b ? s1 : s0;
    uint32_t k0 = r ? s.z : s.x;
    uint32_t k1 = r ? s.w : s.y;
    uint32_t o0, o1;
    threefry2x32(k0, k1, 0u, (uint32_t)i, o0, o1);
    g_skeys[t] = o0 ^ o1;   // xor-fold (32-bit random_bits, partitionable mode)
}

// ---------------- bucket-based stable rank (per (b,round) block) ------------
__global__ void k_rankb() {
    int br = blockIdx.x;                 // 0..3 = b*2+r
    const uint32_t* kp = g_skeys + br * PP;
    __shared__ unsigned long long sorted[PP];   // 32 KB
    __shared__ int prefix[1025];
    __shared__ int cursor[1024];
    __shared__ int cnt[1024];
    __shared__ int wsum[32];
    int t = threadIdx.x;                 // 1024
    uint32_t k0 = kp[t], k1 = kp[t+1024], k2 = kp[t+2048], k3 = kp[t+3072];
    cnt[t] = 0;
    __syncthreads();
    atomicAdd(&cnt[k0 >> 22], 1); atomicAdd(&cnt[k1 >> 22], 1);
    atomicAdd(&cnt[k2 >> 22], 1); atomicAdd(&cnt[k3 >> 22], 1);
    __syncthreads();
    // exclusive scan of cnt -> prefix / cursor
    int v = cnt[t];
    int lane = t & 31, wid = t >> 5;
    int s = v;
#pragma unroll
    for (int o = 1; o < 32; o <<= 1) { int u = __shfl_up_sync(0xffffffffu, s, o); if (lane >= o) s += u; }
    if (lane == 31) wsum[wid] = s;
    __syncthreads();
    if (wid == 0) {
        int ws = wsum[lane];
#pragma unroll
        for (int o = 1; o < 32; o <<= 1) { int u = __shfl_up_sync(0xffffffffu, ws, o); if (lane >= o) ws += u; }
        wsum[lane] = ws;
    }
    __syncthreads();
    int incl = s + (wid > 0 ? wsum[wid-1] : 0);
    prefix[t+1] = incl;
    if (t == 0) prefix[0] = 0;
    cursor[t] = incl - v;
    __syncthreads();
    // scatter (key,idx) packed, grouped by bucket
    {
        int p;
        p = atomicAdd(&cursor[k0 >> 22], 1); sorted[p] = ((unsigned long long)k0 << 32) | (uint32_t)t;
        p = atomicAdd(&cursor[k1 >> 22], 1); sorted[p] = ((unsigned long long)k1 << 32) | (uint32_t)(t+1024);
        p = atomicAdd(&cursor[k2 >> 22], 1); sorted[p] = ((unsigned long long)k2 << 32) | (uint32_t)(t+2048);
        p = atomicAdd(&cursor[k3 >> 22], 1); sorted[p] = ((unsigned long long)k3 << 32) | (uint32_t)(t+3072);
    }
    __syncthreads();
    // rank = prefix[bucket] + count of smaller (key,idx) within bucket
#pragma unroll
    for (int q = 0; q < 4; q++) {
        uint32_t key = (q==0)?k0:(q==1)?k1:(q==2)?k2:k3;
        int i = t + q*1024;
        int bkt = key >> 22;
        int lo = prefix[bkt], hi = prefix[bkt+1];
        unsigned long long mine = ((unsigned long long)key << 32) | (uint32_t)i;
        int r = lo;
        for (int j = lo; j < hi; j++) r += (sorted[j] < mine) ? 1 : 0;
        g_rank[br*PP + i] = (uint32_t)r;
    }
}

__global__ void k_scat0() {
    int t = blockIdx.x * blockDim.x + threadIdx.x;   // 8192
    int b = t >> 12, i = t & 4095;
    g_permA[b*PP + g_rank[(b*2)*PP + i]] = i;
}

__global__ void k_scat1() {
    int t = blockIdx.x * blockDim.x + threadIdx.x;   // 8192
    int b = t >> 12, i = t & 4095;
    uint32_t r1 = g_rank[(b*2+1)*PP + i];
    if (r1 < KK) g_initidx[b*KK + r1] = g_permA[b*PP + i];
}

__global__ void k_initc() {
    int b = blockIdx.x, t = threadIdx.x;        // 1024 threads = 32k x 32d
    int k = t >> 5, d = t & 31;
    g_centers[b*KK*CC + t] = g_obs[(size_t)(b*PP + g_initidx[b*KK + k])*CC + d];
}

// -------- fused kmeans iteration: assign + accumulate + last-block update ----
__global__ void k_iter() {
    int b = blockIdx.x >> 5;
    int pbase = (blockIdx.x & 31) << 7;
    if (!g_active[b]) return;
    __shared__ float sc[KK*CC];
    __shared__ float scn[KK];
    __shared__ float ssum[KK*CC];
    __shared__ float scnt[KK];
    __shared__ float sq[KK];
    __shared__ int slast;
    int t = threadIdx.x;   // 128
    for (int i = t; i < KK*CC; i += 128) { sc[i] = g_centers[b*KK*CC + i]; ssum[i] = 0.f; }
    if (t < KK) scnt[t] = 0.f;
    __syncthreads();
    if (t < KK) {
        float q = 0.f;
#pragma unroll
        for (int d = 0; d < CC; d++) { float c = sc[t*CC + d]; q += c*c; }
        scn[t] = q;
    }
    __syncthreads();
    int p = pbase + t;
    const float* op = g_obs + (size_t)(b*PP + p) * CC;
    float s[CC]; float sn = 0.f;
#pragma unroll
    for (int d = 0; d < CC; d++) { s[d] = op[d]; sn += s[d]*s[d]; }
    float best = 3.4028235e38f; int bi = 0;
    for (int k = 0; k < KK; k++) {
        float dot = 0.f;
#pragma unroll
        for (int d = 0; d < CC; d++) dot += s[d]*sc[k*CC + d];
        float d2 = sn - 2.0f*dot + scn[k];
        if (d2 < best) { best = d2; bi = k; }
    }
    atomicAdd(&scnt[bi], 1.f);
#pragma unroll
    for (int d = 0; d < CC; d++) atomicAdd(&ssum[bi*CC + d], s[d]);
    __syncthreads();
    for (int i = t; i < KK*CC; i += 128) atomicAdd(&g_sums[b*KK*CC + i], ssum[i]);
    if (t < KK) atomicAdd(&g_counts[b*KK + t], scnt[t]);
    __threadfence();
    if (t == 0) {
        int v = atomicAdd(&g_done[b], 1);
        slast = (v == 31);
    }
    __syncthreads();
    if (!slast) return;
    // ---- last block for this batch: center update + convergence ----
    if (t < KK) sq[t] = 0.f;
    __syncthreads();
    int base = b*KK*CC;
#pragma unroll
    for (int q = 0; q < 8; q++) {
        int idx = q*128 + t;        // 0..1023
        int k = idx >> 5;
        float oldc = g_centers[base + idx];
        float cntv = g_counts[b*KK + k];
        float sm   = g_sums[base + idx];
        float nv = (cntv > 0.f) ? (sm / fmaxf(cntv, 1.f)) : oldc;
        float d = nv - oldc;
        atomicAdd(&sq[k], d*d);
        g_centers[base + idx] = nv;
        g_sums[base + idx] = 0.f;
    }
    __syncthreads();
    if (t < KK) g_counts[b*KK + t] = 0.f;
    if (t == 0) {
        float sh = 0.f;
        for (int kk = 0; kk < KK; kk++) sh += sqrtf(sq[kk]);
        int it = g_iter[b] + 1;
        g_iter[b] = it;
        g_active[b] = (it < 20 && sh >= 20.48f) ? 1 : 0;   // TOL*n = 0.005*4096
        g_done[b] = 0;
    }
}

// ---------------- final assignment (always runs) ----------------
__global__ void k_assignF(float* idx_out) {
    int b = blockIdx.x >> 5;
    int pbase = (blockIdx.x & 31) << 7;
    __shared__ float sc[KK*CC];
    __shared__ float scn[KK];
    int t = threadIdx.x;   // 128
    for (int i = t; i < KK*CC; i += 128) sc[i] = g_centers[b*KK*CC + i];
    __syncthreads();
    if (t < KK) {
        float q = 0.f;
#pragma unroll
        for (int d = 0; d < CC; d++) { float c = sc[t*CC + d]; q += c*c; }
        scn[t] = q;
    }
    __syncthreads();
    int p = pbase + t;
    const float* op = g_obs + (size_t)(b*PP + p) * CC;
    float s[CC]; float sn = 0.f;
#pragma unroll
    for (int d = 0; d < CC; d++) { s[d] = op[d]; sn += s[d]*s[d]; }
    float best = 3.4028235e38f; int bi = 0;
    for (int k = 0; k < KK; k++) {
        float dot = 0.f;
#pragma unroll
        for (int d = 0; d < CC; d++) dot += s[d]*sc[k*CC + d];
        float d2 = sn - 2.0f*dot + scn[k];
        if (d2 < best) { best = d2; bi = k; }
    }
    g_assign[b*PP + p] = bi;
    if (idx_out) idx_out[b*PP + p] = (float)bi;
}

// ---------------- cluster segmentation ----------------
__global__ void k_count() {
    int t = blockIdx.x * blockDim.x + threadIdx.x;   // 8192
    int b = t >> 12;
    atomicAdd(&g_cnt[b*KK + g_assign[t]], 1);
}

__global__ void k_tiles() {
    if (threadIdx.x == 0) {
        int off = 0, nt = 0;
        for (int bk = 0; bk < BB*KK; bk++) {
            g_off[bk] = off;
            int c = g_cnt[bk];
            for (int m = 0; m < c; m += 64) { g_tileBK[nt] = bk; g_tileM0[nt] = m; nt++; }
            off += c;
        }
        g_off[BB*KK] = off;
        g_ntiles = nt;
    }
}

__global__ void k_scatter() {
    int t = blockIdx.x * blockDim.x + threadIdx.x;   // 8192
    int b = t >> 12;
    int bk = b*KK + g_assign[t];
    int pos = g_off[bk] + atomicAdd(&g_cursor[bk], 1);
    g_plist[pos] = t;
}

// ---------------- segmented per-cluster 288-dim sums (no big atomics) -------
__global__ void k_sumsF2() {
    int bk = blockIdx.x >> 2, q = blockIdx.x & 3;
    int t = threadIdx.x;                 // 288
    int lo = g_off[bk], hi = g_off[bk+1];
    float acc = 0.f;
    for (int m = lo + q; m < hi; m += 4) {
        int gp = g_plist[m];
        acc += g_patches[(size_t)gp*FF + t];
    }
    if (acc != 0.f || (lo + q < hi))
        atomicAdd(&g_sumsF[bk*FF + t], acc);
}

// ---------------- the two tiny MLPs + softmax ----------------
__global__ void k_mlp(const float* kw1, const float* kb1, const float* kw2, const float* kb2,
                      const float* kw3, const float* kb3,
                      const float* bw1, const float* bb1, const float* bw2, const float* bb2,
                      const float* bw3, const float* bb3) {
    int b = blockIdx.x >> 5, k = blockIdx.x & 31;
    int bk = b*KK + k;
    int t = threadIdx.x;   // 64
    __shared__ float cen[FF];
    __shared__ float h1[HIDD];
    __shared__ float h2[HIDD];
    float dv = fmaxf((float)g_cnt[bk], 1.f);
    for (int f = t; f < FF; f += 64) cen[f] = g_sumsF[(size_t)bk*FF + f] / dv;
    __syncthreads();
    float a = kb1[t];
    for (int f = 0; f < FF; f++) a += cen[f]*kw1[f*HIDD + t];
    h1[t] = fmaxf(a, 0.f);
    __syncthreads();
    a = kb2[t];
#pragma unroll
    for (int i = 0; i < HIDD; i++) a += h1[i]*kw2[i*HIDD + t];
    h2[t] = fmaxf(a, 0.f);
    __syncthreads();
    if (t < NBB) {
        a = kb3[t];
#pragma unroll
        for (int i = 0; i < HIDD; i++) a += h2[i]*kw3[i*NBB + t];
        float m = a;
#pragma unroll
        for (int off = 16; off > 0; off >>= 1) m = fmaxf(m, __shfl_xor_sync(0xffffffffu, m, off));
        float e = expf(a - m);
        float ss = e;
#pragma unroll
        for (int off = 16; off > 0; off >>= 1) ss += __shfl_xor_sync(0xffffffffu, ss, off);
        g_attn[bk*NBB + t] = e / ss;
    }
    __syncthreads();
    a = bb1[t];
    for (int f = 0; f < FF; f++) a += cen[f]*bw1[f*HIDD + t];
    h1[t] = fmaxf(a, 0.f);
    __syncthreads();
    a = bb2[t];
#pragma unroll
    for (int i = 0; i < HIDD; i++) a += h1[i]*bw2[i*HIDD + t];
    h2[t] = fmaxf(a, 0.f);
    __syncthreads();
    a = bb3[t];
#pragma unroll
    for (int i = 0; i < HIDD; i++) a += h2[i]*bw3[i*COUTT + t];
    g_biasv[bk*COUTT + t] = a;
}

// ---------------- kernels = attn @ base_kernels ----------------
__global__ void k_wk(const float* __restrict__ base) {
    int col0 = blockIdx.x * 128;     // column in flattened (f*64+c) space
    int t = threadIdx.x;             // 128
    __shared__ float bt[NBB*128];
    __shared__ float at[BB*KK*NBB];  // 2048
#pragma unroll
    for (int n = 0; n < NBB; n++) bt[n*128 + t] = base[(size_t)n*(FF*COUTT) + col0 + t];
    for (int i = t; i < BB*KK*NBB; i += 128) at[i] = g_attn[i];
    __syncthreads();
    for (int row = 0; row < BB*KK; row++) {
        float acc = 0.f;
#pragma unroll
        for (int n = 0; n < NBB; n++) acc += at[row*NBB + n]*bt[n*128 + t];
        g_wk[(size_t)row*(FF*COUTT) + col0 + t] = acc;
    }
}

// ---------------- cluster-grouped GEMM conv ----------------
__global__ void k_convg(float* __restrict__ out) {
    __shared__ float As[64*36];      // A tile 64px x 32f, stride 36
    __shared__ float Ws[32*64];      // W tile 32f x 64c
    __shared__ int sgp[64];
    int bid = blockIdx.x;
    if (bid >= g_ntiles) return;
    int bk = g_tileBK[bid], m0 = g_tileM0[bid];
    int lo = g_off[bk];
    int rows = g_off[bk+1] - lo - m0;
    if (rows > 64) rows = 64;
    int t = threadIdx.x;             // 256
    if (t < 64) sgp[t] = (t < rows) ? g_plist[lo + m0 + t] : -1;
    __syncthreads();
    int tx = t & 15, ty = t >> 4;
    float acc[4][4];
#pragma unroll
    for (int i = 0; i < 4; i++)
#pragma unroll
        for (int j = 0; j < 4; j++) acc[i][j] = 0.f;
    const float* wkbase = g_wk + (size_t)bk * (FF*COUTT);
    for (int kc = 0; kc < FF; kc += 32) {
#pragma unroll
        for (int u = 0; u < 2; u++) {
            int idx = t + u*256;
            int r = idx >> 3, c4 = idx & 7;
            int gp = sgp[r];
            float4 v = make_float4(0.f, 0.f, 0.f, 0.f);
            if (gp >= 0) v = *(const float4*)(g_patches + (size_t)gp*FF + kc + c4*4);
            *(float4*)(As + r*36 + c4*4) = v;
        }
#pragma unroll
        for (int u = 0; u < 2; u++) {
            int idx = t + u*256;
            int j = idx >> 4, c4 = idx & 15;
            *(float4*)(Ws + j*64 + c4*4) = *(const float4*)(wkbase + (size_t)(kc + j)*COUTT + c4*4);
        }
        __syncthreads();
#pragma unroll
        for (int j = 0; j < 32; j++) {
            float a0 = As[(ty*4+0)*36 + j];
            float a1 = As[(ty*4+1)*36 + j];
            float a2 = As[(ty*4+2)*36 + j];
            float a3 = As[(ty*4+3)*36 + j];
            float4 w = *(const float4*)(Ws + j*64 + tx*4);
            acc[0][0] += a0*w.x; acc[0][1] += a0*w.y; acc[0][2] += a0*w.z; acc[0][3] += a0*w.w;
            acc[1][0] += a1*w.x; acc[1][1] += a1*w.y; acc[1][2] += a1*w.z; acc[1][3] += a1*w.w;
            acc[2][0] += a2*w.x; acc[2][1] += a2*w.y; acc[2][2] += a2*w.z; acc[2][3] += a2*w.w;
            acc[3][0] += a3*w.x; acc[3][1] += a3*w.y; acc[3][2] += a3*w.z; acc[3][3] += a3*w.w;
        }
        __syncthreads();
    }
    int b = bk >> 5;
    float4 bias = *(const float4*)(g_biasv + bk*COUTT + tx*4);
#pragma unroll
    for (int i = 0; i < 4; i++) {
        int gp = sgp[ty*4 + i];
        if (gp < 0) continue;
        int p = gp & 4095;
        size_t ob = (size_t)(b*COUTT + tx*4) * PP + p;
        out[ob          ] = acc[i][0] + bias.x;
        out[ob +   PP   ] = acc[i][1] + bias.y;
        out[ob + 2*PP   ] = acc[i][2] + bias.z;
        out[ob + 3*PP   ] = acc[i][3] + bias.w;
    }
}

// ---------------- launch ----------------
extern "C" void kernel_launch(void* const* d_in, const int* in_sizes, int n_in,
                              void* d_out, int out_size) {
    const float* x    = (const float*)d_in[0];
    const float* base = (const float*)d_in[1];
    const float* kw1 = (const float*)d_in[2];  const float* kb1 = (const float*)d_in[3];
    const float* kw2 = (const float*)d_in[4];  const float* kb2 = (const float*)d_in[5];
    const float* kw3 = (const float*)d_in[6];  const float* kb3 = (const float*)d_in[7];
    const float* bw1 = (const float*)d_in[8];  const float* bb1 = (const float*)d_in[9];
    const float* bw2 = (const float*)d_in[10]; const float* bb2 = (const float*)d_in[11];
    const float* bw3 = (const float*)d_in[12]; const float* bb3 = (const float*)d_in[13];
    float* out = (float*)d_out;

    // JAX key chain (partitionable/fold-like split): key(42) = (0,42)
    uint32_t bk0x, bk0y, bk1x, bk1y;
    threefry2x32(0u, 42u, 0u, 0u, bk0x, bk0y);   // batch 0 key
    threefry2x32(0u, 42u, 0u, 1u, bk1x, bk1y);   // batch 1 key
    uint4 s0, s1;
    {
        uint32_t c0, c1, u, v;
        threefry2x32(bk0x, bk0y, 0u, 1u, u, v); s0.x = u; s0.y = v;   // b0 round-1 subkey
        threefry2x32(bk0x, bk0y, 0u, 0u, c0, c1);                      // b0 carried key
        threefry2x32(c0, c1, 0u, 1u, u, v);     s0.z = u; s0.w = v;   // b0 round-2 subkey
        threefry2x32(bk1x, bk1y, 0u, 1u, u, v); s1.x = u; s1.y = v;
        threefry2x32(bk1x, bk1y, 0u, 0u, c0, c1);
        threefry2x32(c0, c1, 0u, 1u, u, v);     s1.z = u; s1.w = v;
    }

    float* idx_out = (out_size >= BB*COUTT*PP + BB*PP) ? (out + BB*COUTT*PP) : nullptr;

    k_init<<<72, 256>>>();
    k_prep<<<2048, 128>>>(x);
    k_keys<<<16, 1024>>>(s0, s1);
    k_rankb<<<4, 1024>>>();
    k_scat0<<<8, 1024>>>();
    k_scat1<<<8, 1024>>>();
    k_initc<<<2, 1024>>>();
    for (int it = 0; it < 20; it++) {
        k_iter<<<64, 128>>>();
    }
    k_assignF<<<64, 128>>>(idx_out);
    k_count<<<8, 1024>>>();
    k_tiles<<<1, 64>>>();
    k_scatter<<<8, 1024>>>();
    k_sumsF2<<<256, 288>>>();
    k_mlp<<<64, 64>>>(kw1, kb1, kw2, kb2, kw3, kb3, bw1, bb1, bw2, bb2, bw3, bb3);
    k_wk<<<144, 128>>>(base);
    k_convg<<<224, 256>>>(out);
}

// round 5
// speedup vs baseline: 1.2485x; 1.1667x over previous
#include <cuda_runtime.h>
#include <stdint.h>

#define BB 2
#define CC 32
#define HH 64
#define WW 64
#define PP 4096
#define FF 288
#define KK 32
#define NBB 32
#define HIDD 64
#define COUTT 64
#define NBLK 128      // persistent kmeans grid (64 blocks per batch)
#define MAXTILES 256

// ---------------- device scratch (static, no allocation) ----------------
__device__ float    g_patches[BB*PP*FF];   // 9.4 MB
__device__ float    g_obs[BB*PP*CC];       // 1.0 MB
__device__ uint32_t g_rank[BB*2*PP];
__device__ int      g_permA[BB*PP];
__device__ int      g_initidx[BB*KK];
__device__ float    g_centers[BB*KK*CC];
__device__ float    g_sumsB[3][BB*KK*CC];  // rotating triple buffer
__device__ float    g_cntB[3][BB*KK];
__device__ int      g_assign[BB*PP];
__device__ int      g_cnt[BB*KK];
__device__ int      g_cursor[BB*KK];
__device__ int      g_off[BB*KK + 1];
__device__ int      g_plist[BB*PP];
__device__ int      g_tileBK[MAXTILES];
__device__ int      g_tileM0[MAXTILES];
__device__ int      g_ntiles;
__device__ float    g_sumsF[BB*KK*FF];
__device__ float    g_attn[BB*KK*NBB];
__device__ float    g_biasv[BB*KK*COUTT];
__device__ float    g_wk[BB*KK*FF*COUTT];  // 4.7 MB
__device__ unsigned g_bar_cnt;
__device__ unsigned g_bar_gen;

// ---------------- Threefry-2x32 (JAX-compatible core) ----------------
__host__ __device__ inline void threefry2x32(uint32_t k0, uint32_t k1,
                                             uint32_t x0, uint32_t x1,
                                             uint32_t &o0, uint32_t &o1) {
    uint32_t ks2 = k0 ^ k1 ^ 0x1BD11BDAu;
    uint32_t v0 = x0 + k0, v1 = x1 + k1;
#define TF_R(r) { v0 += v1; v1 = (v1 << (r)) | (v1 >> (32 - (r))); v1 ^= v0; }
    TF_R(13) TF_R(15) TF_R(26) TF_R(6)   v0 += k1;  v1 += ks2 + 1u;
    TF_R(17) TF_R(29) TF_R(16) TF_R(24)  v0 += ks2; v1 += k0  + 2u;
    TF_R(13) TF_R(15) TF_R(26) TF_R(6)   v0 += k0;  v1 += k1  + 3u;
    TF_R(17) TF_R(29) TF_R(16) TF_R(24)  v0 += k1;  v1 += ks2 + 4u;
    TF_R(13) TF_R(15) TF_R(26) TF_R(6)   v0 += ks2; v1 += k0  + 5u;
#undef TF_R
    o0 = v0; o1 = v1;
}

// ---------------- software grid barrier (all NBLK blocks resident) --------
__device__ __forceinline__ void grid_sync() {
    __syncthreads();
    if (threadIdx.x == 0) {
        __threadfence();
        unsigned gen = *(volatile unsigned*)&g_bar_gen;
        unsigned arr = atomicAdd(&g_bar_cnt, 1u);
        if (arr == NBLK - 1) {
            g_bar_cnt = 0;
            __threadfence();
            *(volatile unsigned*)&g_bar_gen = gen + 1;
        } else {
            while (*(volatile unsigned*)&g_bar_gen == gen) __nanosleep(32);
        }
    }
    __syncthreads();
}

// ---------------- unfold3 + channel-mean features (coalesced stores) ------
__global__ void k_prep(const float* __restrict__ x) {
    __shared__ float sbuf[4*FF];
    int warp = threadIdx.x >> 5, lane = threadIdx.x & 31;
    int gp = blockIdx.x * 4 + warp;           // 0..8191 = b*4096+p
    int b = gp >> 12, p = gp & 4095;
    int py = p >> 6, px = p & 63;
    const float* xc = x + (size_t)(b*CC + lane) * HH * WW;
    float* prow = sbuf + warp*FF + lane*9;
    float s = 0.f;
#pragma unroll
    for (int i = 0; i < 3; i++) {
        int yy = py + i - 1;
#pragma unroll
        for (int j = 0; j < 3; j++) {
            int xx = px + j - 1;
            float v = (yy >= 0 && yy < HH && xx >= 0 && xx < WW) ? xc[yy*WW + xx] : 0.f;
            prow[i*3 + j] = v;
            s += v;
        }
    }
    g_obs[(size_t)gp * CC + lane] = s / 9.f;
    __syncthreads();
    size_t base = (size_t)(blockIdx.x*4) * FF;
    for (int i = threadIdx.x; i < 4*FF; i += 128) g_patches[base + i] = sbuf[i];
}

// ---------------- bucket-based stable rank, keys fused in ------------------
__global__ void k_rankb(uint4 s0, uint4 s1) {
    int br = blockIdx.x;                 // 0..3 = b*2+r
    int b = br >> 1, r = br & 1;
    uint4 sk4 = b ? s1 : s0;
    uint32_t kk0 = r ? sk4.z : sk4.x;
    uint32_t kk1 = r ? sk4.w : sk4.y;
    __shared__ unsigned long long sorted[PP];   // 32 KB
    __shared__ int prefix[1025];
    __shared__ int cursor[1024];
    __shared__ int cnt[1024];
    __shared__ int wsum[32];
    int t = threadIdx.x;                 // 1024
    uint32_t kq[4];
#pragma unroll
    for (int q = 0; q < 4; q++) {
        uint32_t o0, o1;
        threefry2x32(kk0, kk1, 0u, (uint32_t)(t + q*1024), o0, o1);
        kq[q] = o0 ^ o1;
    }
    cnt[t] = 0;
    __syncthreads();
#pragma unroll
    for (int q = 0; q < 4; q++) atomicAdd(&cnt[kq[q] >> 22], 1);
    __syncthreads();
    int v = cnt[t];
    int lane = t & 31, wid = t >> 5;
    int s = v;
#pragma unroll
    for (int o = 1; o < 32; o <<= 1) { int u = __shfl_up_sync(0xffffffffu, s, o); if (lane >= o) s += u; }
    if (lane == 31) wsum[wid] = s;
    __syncthreads();
    if (wid == 0) {
        int ws = wsum[lane];
#pragma unroll
        for (int o = 1; o < 32; o <<= 1) { int u = __shfl_up_sync(0xffffffffu, ws, o); if (lane >= o) ws += u; }
        wsum[lane] = ws;
    }
    __syncthreads();
    int incl = s + (wid > 0 ? wsum[wid-1] : 0);
    prefix[t+1] = incl;
    if (t == 0) prefix[0] = 0;
    cursor[t] = incl - v;
    __syncthreads();
#pragma unroll
    for (int q = 0; q < 4; q++) {
        int p = atomicAdd(&cursor[kq[q] >> 22], 1);
        sorted[p] = ((unsigned long long)kq[q] << 32) | (uint32_t)(t + q*1024);
    }
    __syncthreads();
#pragma unroll
    for (int q = 0; q < 4; q++) {
        uint32_t key = kq[q];
        int i = t + q*1024;
        int bkt = key >> 22;
        int lo = prefix[bkt], hi = prefix[bkt+1];
        unsigned long long mine = ((unsigned long long)key << 32) | (uint32_t)i;
        int rr = lo;
        for (int j = lo; j < hi; j++) rr += (sorted[j] < mine) ? 1 : 0;
        g_rank[br*PP + i] = (uint32_t)rr;
    }
}

// ------- seed: global init + perm scatter + init-center gather (2 blocks) ---
__global__ void k_seed() {
    int b = blockIdx.x, t = threadIdx.x;   // 2 x 1024
    for (int i = t; i < KK*FF; i += 1024) g_sumsF[b*KK*FF + i] = 0.f;
#pragma unroll
    for (int q = 0; q < 3; q++) {
        if (t < KK*CC) g_sumsB[q][b*KK*CC + t] = 0.f;
        if (t < KK)    g_cntB[q][b*KK + t] = 0.f;
    }
    if (t < KK) { g_cnt[b*KK + t] = 0; g_cursor[b*KK + t] = 0; }
    if (b == 0 && t == 0) { g_bar_cnt = 0; *(volatile unsigned*)&g_bar_gen = 0; }
#pragma unroll
    for (int q = 0; q < 4; q++) {
        int i = t + q*1024;
        g_permA[b*PP + g_rank[(b*2)*PP + i]] = i;
    }
    __syncthreads();
#pragma unroll
    for (int q = 0; q < 4; q++) {
        int i = t + q*1024;
        uint32_t r1 = g_rank[(b*2+1)*PP + i];
        if (r1 < KK) g_initidx[b*KK + r1] = g_permA[b*PP + i];
    }
    __syncthreads();
    if (t < KK*CC) {
        int k = t >> 5, d = t & 31;
        g_centers[b*KK*CC + t] = g_obs[(size_t)(b*PP + g_initidx[b*KK + k])*CC + d];
    }
}

// ---------------- persistent k-means: 20 iters + final assign + segmentation
__global__ void __launch_bounds__(128, 1) k_kmeans(float* idx_out) {
    int bid = blockIdx.x;
    int b = bid >> 6;             // batch
    int sub = bid & 63;           // block within batch
    int t = threadIdx.x;          // 128
    int half = t & 1;
    int lp = t >> 1;              // local point 0..63
    int pi = sub*64 + lp;
    __shared__ __align__(16) float sc[KK*CC];
    __shared__ __align__(16) float ssum[KK*CC];
    __shared__ float scn[KK];
    __shared__ float scnt[KK];
    __shared__ float sq[KK];
    __shared__ float s_shift;

    // point features in registers (persist across all iterations)
    float s[CC]; float sn = 0.f;
    {
        const float* op = g_obs + (size_t)(b*PP + pi) * CC;
#pragma unroll
        for (int d = 0; d < CC; d++) { s[d] = op[d]; sn += s[d]*s[d]; }
    }
    for (int i = t; i < KK*CC; i += 128) sc[i] = g_centers[b*KK*CC + i];
    int active = 1;
    int k0 = half * 16;
    __syncthreads();

    for (int it = 0; it < 20; it++) {
        int buf = it % 3;
        float best = 3.4028235e38f; int bi = 0;
        if (active) {
            for (int i = t; i < KK*CC; i += 128) ssum[i] = 0.f;
            if (t < KK) { scnt[t] = 0.f; sq[t] = 0.f; }
            __syncthreads();
            if (t < KK) {
                float q = 0.f;
#pragma unroll
                for (int d = 0; d < CC; d++) { float c = sc[t*CC + d]; q += c*c; }
                scn[t] = q;
            }
            __syncthreads();
            // assign: 16 clusters per thread, pair-combined
            for (int k = k0; k < k0 + 16; k++) {
                float dot = 0.f;
#pragma unroll
                for (int d = 0; d < CC; d += 4) {
                    float4 c4 = *(const float4*)&sc[k*CC + d];
                    dot += s[d]*c4.x; dot += s[d+1]*c4.y;
                    dot += s[d+2]*c4.z; dot += s[d+3]*c4.w;
                }
                float d2 = sn - 2.0f*dot + scn[k];
                if (d2 < best) { best = d2; bi = k; }
            }
            {
                float ob = __shfl_xor_sync(0xffffffffu, best, 1);
                int   ok = __shfl_xor_sync(0xffffffffu, bi, 1);
                if (ob < best || (ob == best && ok < bi)) { best = ob; bi = ok; }
            }
            if (!half) atomicAdd(&scnt[bi], 1.f);
#pragma unroll
            for (int d = 0; d < 16; d++) atomicAdd(&ssum[bi*CC + k0 + d], s[k0 + d]);
            __syncthreads();
            for (int i = t; i < KK*CC; i += 128) atomicAdd(&g_sumsB[buf][b*KK*CC + i], ssum[i]);
            if (t < KK) atomicAdd(&g_cntB[buf][b*KK + t], scnt[t]);
        }
        grid_sync();
        if (active) {
            // zero the buffer that becomes live at it+2 (safe: its readers done)
            int zb = (it + 2) % 3;
            if (t < 16) g_sumsB[zb][b*KK*CC + sub*16 + t] = 0.f;
            if (t == 16 && sub < KK) g_cntB[zb][b*KK + sub] = 0.f;
            // redundant center update in smem
            for (int i = t; i < KK*CC; i += 128) {
                int k = i >> 5;
                float cntv = __ldcg(&g_cntB[buf][b*KK + k]);
                float sm   = __ldcg(&g_sumsB[buf][b*KK*CC + i]);
                float oldc = sc[i];
                float nv = (cntv > 0.f) ? (sm / fmaxf(cntv, 1.f)) : oldc;
                float d = nv - oldc;
                atomicAdd(&sq[k], d*d);
                sc[i] = nv;
            }
            __syncthreads();
            if (t == 0) {
                float sh = 0.f;
                for (int kk2 = 0; kk2 < KK; kk2++) sh += sqrtf(sq[kk2]);
                s_shift = sh;
            }
            __syncthreads();
            active = ((it + 1) < 20) && (s_shift >= 20.48f);   // TOL*n
        }
    }

    // ---- final assignment with converged centers ----
    __syncthreads();
    if (t < KK) {
        float q = 0.f;
#pragma unroll
        for (int d = 0; d < CC; d++) { float c = sc[t*CC + d]; q += c*c; }
        scn[t] = q;
    }
    __syncthreads();
    float best = 3.4028235e38f; int bi = 0;
    for (int k = k0; k < k0 + 16; k++) {
        float dot = 0.f;
#pragma unroll
        for (int d = 0; d < CC; d += 4) {
            float4 c4 = *(const float4*)&sc[k*CC + d];
            dot += s[d]*c4.x; dot += s[d+1]*c4.y;
            dot += s[d+2]*c4.z; dot += s[d+3]*c4.w;
        }
        float d2 = sn - 2.0f*dot + scn[k];
        if (d2 < best) { best = d2; bi = k; }
    }
    {
        float ob = __shfl_xor_sync(0xffffffffu, best, 1);
        int   ok = __shfl_xor_sync(0xffffffffu, bi, 1);
        if (ob < best || (ob == best && ok < bi)) { best = ob; bi = ok; }
    }
    if (!half) {
        g_assign[b*PP + pi] = bi;
        if (idx_out) idx_out[b*PP + pi] = (float)bi;
        atomicAdd(&g_cnt[b*KK + bi], 1);
    }
    grid_sync();
    // ---- offsets + tile list (single thread; tiny) ----
    if (bid == 0 && t == 0) {
        int off = 0, nt = 0;
        for (int bk = 0; bk < BB*KK; bk++) {
            g_off[bk] = off;
            int c = __ldcg(&g_cnt[bk]);
            for (int m = 0; m < c; m += 64) { g_tileBK[nt] = bk; g_tileM0[nt] = m; nt++; }
            off += c;
        }
        g_off[BB*KK] = off;
        g_ntiles = nt;
    }
    grid_sync();
    // ---- scatter pixel list ----
    if (!half) {
        int bk = b*KK + bi;
        int pos = __ldcg(&g_off[bk]) + atomicAdd(&g_cursor[bk], 1);
        g_plist[pos] = b*PP + pi;
    }
}

// ---------------- segmented per-cluster 288-dim sums -----------------------
__global__ void k_sumsF2() {
    int bk = blockIdx.x >> 2, q = blockIdx.x & 3;
    int t = threadIdx.x;                 // 288
    int lo = g_off[bk], hi = g_off[bk+1];
    float acc = 0.f;
    for (int m = lo + q; m < hi; m += 4) {
        int gp = g_plist[m];
        acc += g_patches[(size_t)gp*FF + t];
    }
    if (lo + q < hi)
        atomicAdd(&g_sumsF[bk*FF + t], acc);
}

// ---------------- the two tiny MLPs + softmax ----------------
__global__ void k_mlp(const float* kw1, const float* kb1, const float* kw2, const float* kb2,
                      const float* kw3, const float* kb3,
                      const float* bw1, const float* bb1, const float* bw2, const float* bb2,
                      const float* bw3, const float* bb3) {
    int b = blockIdx.x >> 5, k = blockIdx.x & 31;
    int bk = b*KK + k;
    int t = threadIdx.x;   // 64
    __shared__ float cen[FF];
    __shared__ float h1[HIDD];
    __shared__ float h2[HIDD];
    float dv = fmaxf((float)g_cnt[bk], 1.f);
    for (int f = t; f < FF; f += 64) cen[f] = g_sumsF[(size_t)bk*FF + f] / dv;
    __syncthreads();
    float a = kb1[t];
    for (int f = 0; f < FF; f++) a += cen[f]*kw1[f*HIDD + t];
    h1[t] = fmaxf(a, 0.f);
    __syncthreads();
    a = kb2[t];
#pragma unroll
    for (int i = 0; i < HIDD; i++) a += h1[i]*kw2[i*HIDD + t];
    h2[t] = fmaxf(a, 0.f);
    __syncthreads();
    if (t < NBB) {
        a = kb3[t];
#pragma unroll
        for (int i = 0; i < HIDD; i++) a += h2[i]*kw3[i*NBB + t];
        float m = a;
#pragma unroll
        for (int off = 16; off > 0; off >>= 1) m = fmaxf(m, __shfl_xor_sync(0xffffffffu, m, off));
        float e = expf(a - m);
        float ss = e;
#pragma unroll
        for (int off = 16; off > 0; off >>= 1) ss += __shfl_xor_sync(0xffffffffu, ss, off);
        g_attn[bk*NBB + t] = e / ss;
    }
    __syncthreads();
    a = bb1[t];
    for (int f = 0; f < FF; f++) a += cen[f]*bw1[f*HIDD + t];
    h1[t] = fmaxf(a, 0.f);
    __syncthreads();
    a = bb2[t];
#pragma unroll
    for (int i = 0; i < HIDD; i++) a += h1[i]*bw2[i*HIDD + t];
    h2[t] = fmaxf(a, 0.f);
    __syncthreads();
    a = bb3[t];
#pragma unroll
    for (int i = 0; i < HIDD; i++) a += h2[i]*bw3[i*COUTT + t];
    g_biasv[bk*COUTT + t] = a;
}

// ---------------- kernels = attn @ base_kernels ----------------
__global__ void k_wk(const float* __restrict__ base) {
    int col0 = blockIdx.x * 128;
    int t = threadIdx.x;             // 128
    __shared__ float bt[NBB*128];
    __shared__ float at[BB*KK*NBB];
#pragma unroll
    for (int n = 0; n < NBB; n++) bt[n*128 + t] = base[(size_t)n*(FF*COUTT) + col0 + t];
    for (int i = t; i < BB*KK*NBB; i += 128) at[i] = g_attn[i];
    __syncthreads();
    for (int row = 0; row < BB*KK; row++) {
        float acc = 0.f;
#pragma unroll
        for (int n = 0; n < NBB; n++) acc += at[row*NBB + n]*bt[n*128 + t];
        g_wk[(size_t)row*(FF*COUTT) + col0 + t] = acc;
    }
}

// ---------------- cluster-grouped GEMM conv ----------------
__global__ void k_convg(float* __restrict__ out) {
    __shared__ float As[64*36];
    __shared__ float Ws[32*64];
    __shared__ int sgp[64];
    int bid = blockIdx.x;
    if (bid >= g_ntiles) return;
    int bk = g_tileBK[bid], m0 = g_tileM0[bid];
    int lo = g_off[bk];
    int rows = g_off[bk+1] - lo - m0;
    if (rows > 64) rows = 64;
    int t = threadIdx.x;             // 256
    if (t < 64) sgp[t] = (t < rows) ? g_plist[lo + m0 + t] : -1;
    __syncthreads();
    int tx = t & 15, ty = t >> 4;
    float acc[4][4];
#pragma unroll
    for (int i = 0; i < 4; i++)
#pragma unroll
        for (int j = 0; j < 4; j++) acc[i][j] = 0.f;
    const float* wkbase = g_wk + (size_t)bk * (FF*COUTT);
    for (int kc = 0; kc < FF; kc += 32) {
#pragma unroll
        for (int u = 0; u < 2; u++) {
            int idx = t + u*256;
            int r = idx >> 3, c4 = idx & 7;
            int gp = sgp[r];
            float4 v = make_float4(0.f, 0.f, 0.f, 0.f);
            if (gp >= 0) v = *(const float4*)(g_patches + (size_t)gp*FF + kc + c4*4);
            *(float4*)(As + r*36 + c4*4) = v;
        }
#pragma unroll
        for (int u = 0; u < 2; u++) {
            int idx = t + u*256;
            int j = idx >> 4, c4 = idx & 15;
            *(float4*)(Ws + j*64 + c4*4) = *(const float4*)(wkbase + (size_t)(kc + j)*COUTT + c4*4);
        }
        __syncthreads();
#pragma unroll
        for (int j = 0; j < 32; j++) {
            float a0 = As[(ty*4+0)*36 + j];
            float a1 = As[(ty*4+1)*36 + j];
            float a2 = As[(ty*4+2)*36 + j];
            float a3 = As[(ty*4+3)*36 + j];
            float4 w = *(const float4*)(Ws + j*64 + tx*4);
            acc[0][0] += a0*w.x; acc[0][1] += a0*w.y; acc[0][2] += a0*w.z; acc[0][3] += a0*w.w;
            acc[1][0] += a1*w.x; acc[1][1] += a1*w.y; acc[1][2] += a1*w.z; acc[1][3] += a1*w.w;
            acc[2][0] += a2*w.x; acc[2][1] += a2*w.y; acc[2][2] += a2*w.z; acc[2][3] += a2*w.w;
            acc[3][0] += a3*w.x; acc[3][1] += a3*w.y; acc[3][2] += a3*w.z; acc[3][3] += a3*w.w;
        }
        __syncthreads();
    }
    int b = bk >> 5;
    float4 bias = *(const float4*)(g_biasv + bk*COUTT + tx*4);
#pragma unroll
    for (int i = 0; i < 4; i++) {
        int gp = sgp[ty*4 + i];
        if (gp < 0) continue;
        int p = gp & 4095;
        size_t ob = (size_t)(b*COUTT + tx*4) * PP + p;
        out[ob          ] = acc[i][0] + bias.x;
        out[ob +   PP   ] = acc[i][1] + bias.y;
        out[ob + 2*PP   ] = acc[i][2] + bias.z;
        out[ob + 3*PP   ] = acc[i][3] + bias.w;
    }
}

// ---------------- launch ----------------
extern "C" void kernel_launch(void* const* d_in, const int* in_sizes, int n_in,
                              void* d_out, int out_size) {
    const float* x    = (const float*)d_in[0];
    const float* base = (const float*)d_in[1];
    const float* kw1 = (const float*)d_in[2];  const float* kb1 = (const float*)d_in[3];
    const float* kw2 = (const float*)d_in[4];  const float* kb2 = (const float*)d_in[5];
    const float* kw3 = (const float*)d_in[6];  const float* kb3 = (const float*)d_in[7];
    const float* bw1 = (const float*)d_in[8];  const float* bb1 = (const float*)d_in[9];
    const float* bw2 = (const float*)d_in[10]; const float* bb2 = (const float*)d_in[11];
    const float* bw3 = (const float*)d_in[12]; const float* bb3 = (const float*)d_in[13];
    float* out = (float*)d_out;

    // JAX key chain (partitionable/fold-like split): key(42) = (0,42)
    uint32_t bk0x, bk0y, bk1x, bk1y;
    threefry2x32(0u, 42u, 0u, 0u, bk0x, bk0y);   // batch 0 key
    threefry2x32(0u, 42u, 0u, 1u, bk1x, bk1y);   // batch 1 key
    uint4 s0, s1;
    {
        uint32_t c0, c1, u, v;
        threefry2x32(bk0x, bk0y, 0u, 1u, u, v); s0.x = u; s0.y = v;
        threefry2x32(bk0x, bk0y, 0u, 0u, c0, c1);
        threefry2x32(c0, c1, 0u, 1u, u, v);     s0.z = u; s0.w = v;
        threefry2x32(bk1x, bk1y, 0u, 1u, u, v); s1.x = u; s1.y = v;
        threefry2x32(bk1x, bk1y, 0u, 0u, c0, c1);
        threefry2x32(c0, c1, 0u, 1u, u, v);     s1.z = u; s1.w = v;
    }

    float* idx_out = (out_size >= BB*COUTT*PP + BB*PP) ? (out + BB*COUTT*PP) : nullptr;

    k_prep<<<2048, 128>>>(x);
    k_rankb<<<4, 1024>>>(s0, s1);
    k_seed<<<2, 1024>>>();
    k_kmeans<<<NBLK, 128>>>(idx_out);
    k_sumsF2<<<256, 288>>>();
    k_mlp<<<64, 64>>>(kw1, kb1, kw2, kb2, kw3, kb3, bw1, bb1, bw2, bb2, bw3, bb3);
    k_wk<<<144, 128>>>(base);
    k_convg<<<MAXTILES, 256>>>(out);
}

// round 6
// speedup vs baseline: 1.3692x; 1.0967x over previous
#include <cuda_runtime.h>
#include <stdint.h>

#define BB 2
#define CC 32
#define HH 64
#define WW 64
#define PP 4096
#define FF 288
#define KK 32
#define NBB 32
#define HIDD 64
#define COUTT 64
#define NBLK 128      // persistent kmeans grid (64 blocks per batch)
#define MAXTILES 256

// ---------------- device scratch (static, no allocation) ----------------
__device__ float    g_patches[BB*PP*FF];   // 9.4 MB
__device__ float    g_obs[BB*PP*CC];       // 1.0 MB
__device__ uint32_t g_rank[BB*2*PP];
__device__ int      g_permA[BB*PP];
__device__ int      g_initidx[BB*KK];
__device__ float    g_centers[BB*KK*CC];
__device__ float    g_sumsB[3][BB*KK*CC];  // rotating triple buffer
__device__ float    g_cntB[3][BB*KK];
__device__ int      g_cnt[BB*KK];
__device__ int      g_cursor[BB*KK];
__device__ int      g_off[BB*KK + 1];
__device__ int      g_plist[BB*PP];
__device__ int      g_tileBK[MAXTILES];
__device__ int      g_tileM0[MAXTILES];
__device__ int      g_ntiles;
__device__ float    g_sumsF[BB*KK*FF];
__device__ float    g_attn[BB*KK*NBB];
__device__ float    g_biasv[BB*KK*COUTT];
__device__ float    g_wk[BB*KK*FF*COUTT];  // 4.7 MB
__device__ unsigned g_bcnt[BB];            // per-batch barrier
__device__ unsigned g_bgen[BB];
__device__ unsigned g_gcnt;                // global barrier
__device__ unsigned g_ggen;

// ---------------- Threefry-2x32 (JAX-compatible core) ----------------
__host__ __device__ inline void threefry2x32(uint32_t k0, uint32_t k1,
                                             uint32_t x0, uint32_t x1,
                                             uint32_t &o0, uint32_t &o1) {
    uint32_t ks2 = k0 ^ k1 ^ 0x1BD11BDAu;
    uint32_t v0 = x0 + k0, v1 = x1 + k1;
#define TF_R(r) { v0 += v1; v1 = (v1 << (r)) | (v1 >> (32 - (r))); v1 ^= v0; }
    TF_R(13) TF_R(15) TF_R(26) TF_R(6)   v0 += k1;  v1 += ks2 + 1u;
    TF_R(17) TF_R(29) TF_R(16) TF_R(24)  v0 += ks2; v1 += k0  + 2u;
    TF_R(13) TF_R(15) TF_R(26) TF_R(6)   v0 += k0;  v1 += k1  + 3u;
    TF_R(17) TF_R(29) TF_R(16) TF_R(24)  v0 += k1;  v1 += ks2 + 4u;
    TF_R(13) TF_R(15) TF_R(26) TF_R(6)   v0 += ks2; v1 += k0  + 5u;
#undef TF_R
    o0 = v0; o1 = v1;
}

// ---------------- barriers (sense-reversing, tight poll) -------------------
__device__ __forceinline__ void batch_sync(int b) {
    __syncthreads();
    if (threadIdx.x == 0) {
        __threadfence();
        unsigned gen = ((volatile unsigned*)g_bgen)[b];
        if (atomicAdd(&g_bcnt[b], 1u) == (NBLK/2 - 1)) {
            g_bcnt[b] = 0;
            __threadfence();
            atomicExch(&g_bgen[b], gen + 1u);
        } else {
            while (((volatile unsigned*)g_bgen)[b] == gen) { }
        }
        __threadfence();
    }
    __syncthreads();
}

__device__ __forceinline__ void grid_sync() {
    __syncthreads();
    if (threadIdx.x == 0) {
        __threadfence();
        unsigned gen = *(volatile unsigned*)&g_ggen;
        if (atomicAdd(&g_gcnt, 1u) == (NBLK - 1)) {
            g_gcnt = 0;
            __threadfence();
            atomicExch(&g_ggen, gen + 1u);
        } else {
            while (*(volatile unsigned*)&g_ggen == gen) { }
        }
        __threadfence();
    }
    __syncthreads();
}

// ---------------- unfold3 + channel-mean features (coalesced stores) ------
__global__ void k_prep(const float* __restrict__ x) {
    __shared__ float sbuf[4*FF];
    int warp = threadIdx.x >> 5, lane = threadIdx.x & 31;
    int gp = blockIdx.x * 4 + warp;           // 0..8191 = b*4096+p
    int b = gp >> 12, p = gp & 4095;
    int py = p >> 6, px = p & 63;
    const float* xc = x + (size_t)(b*CC + lane) * HH * WW;
    float* prow = sbuf + warp*FF + lane*9;
    float s = 0.f;
#pragma unroll
    for (int i = 0; i < 3; i++) {
        int yy = py + i - 1;
#pragma unroll
        for (int j = 0; j < 3; j++) {
            int xx = px + j - 1;
            float v = (yy >= 0 && yy < HH && xx >= 0 && xx < WW) ? xc[yy*WW + xx] : 0.f;
            prow[i*3 + j] = v;
            s += v;
        }
    }
    g_obs[(size_t)gp * CC + lane] = s / 9.f;
    __syncthreads();
    size_t base = (size_t)(blockIdx.x*4) * FF;
    for (int i = threadIdx.x; i < 4*FF; i += 128) g_patches[base + i] = sbuf[i];
}

// ---------------- bucket-based stable rank, keys fused in ------------------
__global__ void k_rankb(uint4 s0, uint4 s1) {
    int br = blockIdx.x;                 // 0..3 = b*2+r
    int b = br >> 1, r = br & 1;
    uint4 sk4 = b ? s1 : s0;
    uint32_t kk0 = r ? sk4.z : sk4.x;
    uint32_t kk1 = r ? sk4.w : sk4.y;
    __shared__ unsigned long long sorted[PP];   // 32 KB
    __shared__ int prefix[1025];
    __shared__ int cursor[1024];
    __shared__ int cnt[1024];
    __shared__ int wsum[32];
    int t = threadIdx.x;                 // 1024
    uint32_t kq[4];
#pragma unroll
    for (int q = 0; q < 4; q++) {
        uint32_t o0, o1;
        threefry2x32(kk0, kk1, 0u, (uint32_t)(t + q*1024), o0, o1);
        kq[q] = o0 ^ o1;
    }
    cnt[t] = 0;
    __syncthreads();
#pragma unroll
    for (int q = 0; q < 4; q++) atomicAdd(&cnt[kq[q] >> 22], 1);
    __syncthreads();
    int v = cnt[t];
    int lane = t & 31, wid = t >> 5;
    int s = v;
#pragma unroll
    for (int o = 1; o < 32; o <<= 1) { int u = __shfl_up_sync(0xffffffffu, s, o); if (lane >= o) s += u; }
    if (lane == 31) wsum[wid] = s;
    __syncthreads();
    if (wid == 0) {
        int ws = wsum[lane];
#pragma unroll
        for (int o = 1; o < 32; o <<= 1) { int u = __shfl_up_sync(0xffffffffu, ws, o); if (lane >= o) ws += u; }
        wsum[lane] = ws;
    }
    __syncthreads();
    int incl = s + (wid > 0 ? wsum[wid-1] : 0);
    prefix[t+1] = incl;
    if (t == 0) prefix[0] = 0;
    cursor[t] = incl - v;
    __syncthreads();
#pragma unroll
    for (int q = 0; q < 4; q++) {
        int p = atomicAdd(&cursor[kq[q] >> 22], 1);
        sorted[p] = ((unsigned long long)kq[q] << 32) | (uint32_t)(t + q*1024);
    }
    __syncthreads();
#pragma unroll
    for (int q = 0; q < 4; q++) {
        uint32_t key = kq[q];
        int i = t + q*1024;
        int bkt = key >> 22;
        int lo = prefix[bkt], hi = prefix[bkt+1];
        unsigned long long mine = ((unsigned long long)key << 32) | (uint32_t)i;
        int rr = lo;
        for (int j = lo; j < hi; j++) rr += (sorted[j] < mine) ? 1 : 0;
        g_rank[br*PP + i] = (uint32_t)rr;
    }
}

// ------- seed: global init + perm scatter + init-center gather (2 blocks) ---
__global__ void k_seed() {
    int b = blockIdx.x, t = threadIdx.x;   // 2 x 1024
    for (int i = t; i < KK*FF; i += 1024) g_sumsF[b*KK*FF + i] = 0.f;
#pragma unroll
    for (int q = 0; q < 3; q++) {
        if (t < KK*CC) g_sumsB[q][b*KK*CC + t] = 0.f;
        if (t < KK)    g_cntB[q][b*KK + t] = 0.f;
    }
    if (t < KK) { g_cnt[b*KK + t] = 0; g_cursor[b*KK + t] = 0; }
    if (t == 0) { g_bcnt[b] = 0; g_bgen[b] = 0; }
    if (b == 0 && t == 0) { g_gcnt = 0; g_ggen = 0; }
#pragma unroll
    for (int q = 0; q < 4; q++) {
        int i = t + q*1024;
        g_permA[b*PP + g_rank[(b*2)*PP + i]] = i;
    }
    __syncthreads();
#pragma unroll
    for (int q = 0; q < 4; q++) {
        int i = t + q*1024;
        uint32_t r1 = g_rank[(b*2+1)*PP + i];
        if (r1 < KK) g_initidx[b*KK + r1] = g_permA[b*PP + i];
    }
    __syncthreads();
    if (t < KK*CC) {
        int k = t >> 5, d = t & 31;
        g_centers[b*KK*CC + t] = g_obs[(size_t)(b*PP + g_initidx[b*KK + k])*CC + d];
    }
}

// --- persistent k-means + final assign + segmentation + sumsF + MLPs -------
__global__ void __launch_bounds__(128, 1) k_kmeans(
    float* idx_out,
    const float* __restrict__ kw1, const float* __restrict__ kb1,
    const float* __restrict__ kw2, const float* __restrict__ kb2,
    const float* __restrict__ kw3, const float* __restrict__ kb3,
    const float* __restrict__ bw1, const float* __restrict__ bb1,
    const float* __restrict__ bw2, const float* __restrict__ bb2,
    const float* __restrict__ bw3, const float* __restrict__ bb3)
{
    int bid = blockIdx.x;
    int b = bid >> 6;             // batch
    int sub = bid & 63;           // block within batch
    int t = threadIdx.x;          // 128
    int half = t & 1;
    int lp = t >> 1;              // local point 0..63
    int pi = sub*64 + lp;
    __shared__ __align__(16) float sc[KK*CC];
    __shared__ __align__(16) float ssum[KK*CC];
    __shared__ float scn[KK];
    __shared__ float scnt[KK];
    __shared__ float sq[KK];
    __shared__ float s_shift;

    // point features in registers (persist across all iterations)
    float s[CC]; float sn = 0.f;
    {
        const float* op = g_obs + (size_t)(b*PP + pi) * CC;
#pragma unroll
        for (int d = 0; d < CC; d++) { s[d] = op[d]; sn += s[d]*s[d]; }
    }
    for (int i = t; i < KK*CC; i += 128) sc[i] = g_centers[b*KK*CC + i];
    int k0 = half * 16;
    __syncthreads();

    for (int it = 0; it < 20; it++) {
        int buf = it % 3;
        for (int i = t; i < KK*CC; i += 128) ssum[i] = 0.f;
        if (t < KK) { scnt[t] = 0.f; sq[t] = 0.f; }
        __syncthreads();
        if (t < KK) {
            float q = 0.f;
#pragma unroll
            for (int d = 0; d < CC; d++) { float c = sc[t*CC + d]; q += c*c; }
            scn[t] = q;
        }
        __syncthreads();
        float best = 3.4028235e38f; int bi = 0;
        for (int k = k0; k < k0 + 16; k++) {
            float dot = 0.f;
#pragma unroll
            for (int d = 0; d < CC; d += 4) {
                float4 c4 = *(const float4*)&sc[k*CC + d];
                dot += s[d]*c4.x; dot += s[d+1]*c4.y;
                dot += s[d+2]*c4.z; dot += s[d+3]*c4.w;
            }
            float d2 = sn - 2.0f*dot + scn[k];
            if (d2 < best) { best = d2; bi = k; }
        }
        {
            float ob = __shfl_xor_sync(0xffffffffu, best, 1);
            int   ok = __shfl_xor_sync(0xffffffffu, bi, 1);
            if (ob < best || (ob == best && ok < bi)) { best = ob; bi = ok; }
        }
        if (!half) atomicAdd(&scnt[bi], 1.f);
#pragma unroll
        for (int d = 0; d < 16; d++) atomicAdd(&ssum[bi*CC + k0 + d], s[k0 + d]);
        __syncthreads();
        for (int i = t; i < KK*CC; i += 128) atomicAdd(&g_sumsB[buf][b*KK*CC + i], ssum[i]);
        if (t < KK) atomicAdd(&g_cntB[buf][b*KK + t], scnt[t]);
        batch_sync(b);
        // zero the buffer that becomes live at it+2 (its readers are done)
        int zb = (it + 2) % 3;
        if (t < 16) g_sumsB[zb][b*KK*CC + sub*16 + t] = 0.f;
        if (t == 16 && sub < KK) g_cntB[zb][b*KK + sub] = 0.f;
        // redundant center update in smem (identical in every block of batch)
        for (int i = t; i < KK*CC; i += 128) {
            int k = i >> 5;
            float cntv = __ldcg(&g_cntB[buf][b*KK + k]);
            float sm   = __ldcg(&g_sumsB[buf][b*KK*CC + i]);
            float oldc = sc[i];
            float nv = (cntv > 0.f) ? (sm / fmaxf(cntv, 1.f)) : oldc;
            float d = nv - oldc;
            atomicAdd(&sq[k], d*d);
            sc[i] = nv;
        }
        __syncthreads();
        if (t == 0) {
            float sh = 0.f;
            for (int kk2 = 0; kk2 < KK; kk2++) sh += sqrtf(sq[kk2]);
            s_shift = sh;
        }
        __syncthreads();
        if ((it + 1) >= 20 || s_shift < 20.48f) break;   // TOL*n = 0.005*4096
    }

    // ---- final assignment with converged centers ----
    __syncthreads();
    if (t < KK) {
        float q = 0.f;
#pragma unroll
        for (int d = 0; d < CC; d++) { float c = sc[t*CC + d]; q += c*c; }
        scn[t] = q;
    }
    __syncthreads();
    float best = 3.4028235e38f; int bi = 0;
    for (int k = k0; k < k0 + 16; k++) {
        float dot = 0.f;
#pragma unroll
        for (int d = 0; d < CC; d += 4) {
            float4 c4 = *(const float4*)&sc[k*CC + d];
            dot += s[d]*c4.x; dot += s[d+1]*c4.y;
            dot += s[d+2]*c4.z; dot += s[d+3]*c4.w;
        }
        float d2 = sn - 2.0f*dot + scn[k];
        if (d2 < best) { best = d2; bi = k; }
    }
    {
        float ob = __shfl_xor_sync(0xffffffffu, best, 1);
        int   ok = __shfl_xor_sync(0xffffffffu, bi, 1);
        if (ob < best || (ob == best && ok < bi)) { best = ob; bi = ok; }
    }
    if (!half) {
        if (idx_out) idx_out[b*PP + pi] = (float)bi;
        atomicAdd(&g_cnt[b*KK + bi], 1);
    }
    grid_sync();
    // ---- offsets + tile list (single thread; tiny) ----
    if (bid == 0 && t == 0) {
        int off = 0, nt = 0;
        for (int bk = 0; bk < BB*KK; bk++) {
            g_off[bk] = off;
            int c = __ldcg(&g_cnt[bk]);
            for (int m = 0; m < c; m += 64) { g_tileBK[nt] = bk; g_tileM0[nt] = m; nt++; }
            off += c;
        }
        g_off[BB*KK] = off;
        g_ntiles = nt;
    }
    grid_sync();
    // ---- scatter pixel list ----
    if (!half) {
        int bk = b*KK + bi;
        int pos = __ldcg(&g_off[bk]) + atomicAdd(&g_cursor[bk], 1);
        g_plist[pos] = b*PP + pi;
    }
    grid_sync();
    // ---- segmented per-cluster 288-dim sums (2 quad-segments per block) ----
#pragma unroll
    for (int j = 0; j < 2; j++) {
        int w = bid + j*NBLK;            // 0..255
        int bk = w >> 2, quad = w & 3;
        int lo = __ldcg(&g_off[bk]), hi = __ldcg(&g_off[bk+1]);
        float a0 = 0.f, a1 = 0.f, a2 = 0.f;
        for (int m = lo + quad; m < hi; m += 4) {
            int gp = __ldcg(&g_plist[m]);
            const float* pr = g_patches + (size_t)gp*FF;
            a0 += pr[t]; a1 += pr[t+128];
            if (t < 32) a2 += pr[t+256];
        }
        if (lo + quad < hi) {
            atomicAdd(&g_sumsF[bk*FF + t], a0);
            atomicAdd(&g_sumsF[bk*FF + t + 128], a1);
            if (t < 32) atomicAdd(&g_sumsF[bk*FF + t + 256], a2);
        }
    }
    grid_sync();
    // ---- the two tiny MLPs + softmax (blocks 0..63, one per bk) ----
    if (bid >= BB*KK) return;
    {
        int bk = bid;
        __shared__ float cen[FF];
        __shared__ float h1[HIDD];
        __shared__ float h2[HIDD];
        float dv = fmaxf((float)__ldcg(&g_cnt[bk]), 1.f);
        for (int f = t; f < FF; f += 128) cen[f] = __ldcg(&g_sumsF[(size_t)bk*FF + f]) / dv;
        __syncthreads();
        if (t < HIDD) {
            float a = kb1[t];
            for (int f = 0; f < FF; f++) a += cen[f]*kw1[f*HIDD + t];
            h1[t] = fmaxf(a, 0.f);
        }
        __syncthreads();
        if (t < HIDD) {
            float a = kb2[t];
#pragma unroll
            for (int i = 0; i < HIDD; i++) a += h1[i]*kw2[i*HIDD + t];
            h2[t] = fmaxf(a, 0.f);
        }
        __syncthreads();
        if (t < NBB) {
            float a = kb3[t];
#pragma unroll
            for (int i = 0; i < HIDD; i++) a += h2[i]*kw3[i*NBB + t];
            float m = a;
#pragma unroll
            for (int off = 16; off > 0; off >>= 1) m = fmaxf(m, __shfl_xor_sync(0xffffffffu, m, off));
            float e = expf(a - m);
            float ss = e;
#pragma unroll
            for (int off = 16; off > 0; off >>= 1) ss += __shfl_xor_sync(0xffffffffu, ss, off);
            g_attn[bk*NBB + t] = e / ss;
        }
        __syncthreads();
        if (t < HIDD) {
            float a = bb1[t];
            for (int f = 0; f < FF; f++) a += cen[f]*bw1[f*HIDD + t];
            h1[t] = fmaxf(a, 0.f);
        }
        __syncthreads();
        if (t < HIDD) {
            float a = bb2[t];
#pragma unroll
            for (int i = 0; i < HIDD; i++) a += h1[i]*bw2[i*HIDD + t];
            h2[t] = fmaxf(a, 0.f);
        }
        __syncthreads();
        if (t < COUTT) {
            float a = bb3[t];
#pragma unroll
            for (int i = 0; i < HIDD; i++) a += h2[i]*bw3[i*COUTT + t];
            g_biasv[bk*COUTT + t] = a;
        }
    }
}

// ---------------- kernels = attn @ base_kernels ----------------
__global__ void k_wk(const float* __restrict__ base) {
    int col0 = blockIdx.x * 128;
    int t = threadIdx.x;             // 128
    __shared__ float bt[NBB*128];
    __shared__ float at[BB*KK*NBB];
#pragma unroll
    for (int n = 0; n < NBB; n++) bt[n*128 + t] = base[(size_t)n*(FF*COUTT) + col0 + t];
    for (int i = t; i < BB*KK*NBB; i += 128) at[i] = g_attn[i];
    __syncthreads();
    for (int row = 0; row < BB*KK; row++) {
        float acc = 0.f;
#pragma unroll
        for (int n = 0; n < NBB; n++) acc += at[row*NBB + n]*bt[n*128 + t];
        g_wk[(size_t)row*(FF*COUTT) + col0 + t] = acc;
    }
}

// ---------------- cluster-grouped GEMM conv ----------------
__global__ void k_convg(float* __restrict__ out) {
    __shared__ float As[64*36];
    __shared__ float Ws[32*64];
    __shared__ int sgp[64];
    int bid = blockIdx.x;
    if (bid >= g_ntiles) return;
    int bk = g_tileBK[bid], m0 = g_tileM0[bid];
    int lo = g_off[bk];
    int rows = g_off[bk+1] - lo - m0;
    if (rows > 64) rows = 64;
    int t = threadIdx.x;             // 256
    if (t < 64) sgp[t] = (t < rows) ? g_plist[lo + m0 + t] : -1;
    __syncthreads();
    int tx = t & 15, ty = t >> 4;
    float acc[4][4];
#pragma unroll
    for (int i = 0; i < 4; i++)
#pragma unroll
        for (int j = 0; j < 4; j++) acc[i][j] = 0.f;
    const float* wkbase = g_wk + (size_t)bk * (FF*COUTT);
    for (int kc = 0; kc < FF; kc += 32) {
#pragma unroll
        for (int u = 0; u < 2; u++) {
            int idx = t + u*256;
            int r = idx >> 3, c4 = idx & 7;
            int gp = sgp[r];
            float4 v = make_float4(0.f, 0.f, 0.f, 0.f);
            if (gp >= 0) v = *(const float4*)(g_patches + (size_t)gp*FF + kc + c4*4);
            *(float4*)(As + r*36 + c4*4) = v;
        }
#pragma unroll
        for (int u = 0; u < 2; u++) {
            int idx = t + u*256;
            int j = idx >> 4, c4 = idx & 15;
            *(float4*)(Ws + j*64 + c4*4) = *(const float4*)(wkbase + (size_t)(kc + j)*COUTT + c4*4);
        }
        __syncthreads();
#pragma unroll
        for (int j = 0; j < 32; j++) {
            float a0 = As[(ty*4+0)*36 + j];
            float a1 = As[(ty*4+1)*36 + j];
            float a2 = As[(ty*4+2)*36 + j];
            float a3 = As[(ty*4+3)*36 + j];
            float4 w = *(const float4*)(Ws + j*64 + tx*4);
            acc[0][0] += a0*w.x; acc[0][1] += a0*w.y; acc[0][2] += a0*w.z; acc[0][3] += a0*w.w;
            acc[1][0] += a1*w.x; acc[1][1] += a1*w.y; acc[1][2] += a1*w.z; acc[1][3] += a1*w.w;
            acc[2][0] += a2*w.x; acc[2][1] += a2*w.y; acc[2][2] += a2*w.z; acc[2][3] += a2*w.w;
            acc[3][0] += a3*w.x; acc[3][1] += a3*w.y; acc[3][2] += a3*w.z; acc[3][3] += a3*w.w;
        }
        __syncthreads();
    }
    int b = bk >> 5;
    float4 bias = *(const float4*)(g_biasv + bk*COUTT + tx*4);
#pragma unroll
    for (int i = 0; i < 4; i++) {
        int gp = sgp[ty*4 + i];
        if (gp < 0) continue;
        int p = gp & 4095;
        size_t ob = (size_t)(b*COUTT + tx*4) * PP + p;
        out[ob          ] = acc[i][0] + bias.x;
        out[ob +   PP   ] = acc[i][1] + bias.y;
        out[ob + 2*PP   ] = acc[i][2] + bias.z;
        out[ob + 3*PP   ] = acc[i][3] + bias.w;
    }
}

// ---------------- launch ----------------
extern "C" void kernel_launch(void* const* d_in, const int* in_sizes, int n_in,
                              void* d_out, int out_size) {
    const float* x    = (const float*)d_in[0];
    const float* base = (const float*)d_in[1];
    const float* kw1 = (const float*)d_in[2];  const float* kb1 = (const float*)d_in[3];
    const float* kw2 = (const float*)d_in[4];  const float* kb2 = (const float*)d_in[5];
    const float* kw3 = (const float*)d_in[6];  const float* kb3 = (const float*)d_in[7];
    const float* bw1 = (const float*)d_in[8];  const float* bb1 = (const float*)d_in[9];
    const float* bw2 = (const float*)d_in[10]; const float* bb2 = (const float*)d_in[11];
    const float* bw3 = (const float*)d_in[12]; const float* bb3 = (const float*)d_in[13];
    float* out = (float*)d_out;

    // JAX key chain (partitionable/fold-like split): key(42) = (0,42)
    uint32_t bk0x, bk0y, bk1x, bk1y;
    threefry2x32(0u, 42u, 0u, 0u, bk0x, bk0y);   // batch 0 key
    threefry2x32(0u, 42u, 0u, 1u, bk1x, bk1y);   // batch 1 key
    uint4 s0, s1;
    {
        uint32_t c0, c1, u, v;
        threefry2x32(bk0x, bk0y, 0u, 1u, u, v); s0.x = u; s0.y = v;
        threefry2x32(bk0x, bk0y, 0u, 0u, c0, c1);
        threefry2x32(c0, c1, 0u, 1u, u, v);     s0.z = u; s0.w = v;
        threefry2x32(bk1x, bk1y, 0u, 1u, u, v); s1.x = u; s1.y = v;
        threefry2x32(bk1x, bk1y, 0u, 0u, c0, c1);
        threefry2x32(c0, c1, 0u, 1u, u, v);     s1.z = u; s1.w = v;
    }

    float* idx_out = (out_size >= BB*COUTT*PP + BB*PP) ? (out + BB*COUTT*PP) : nullptr;

    k_prep<<<2048, 128>>>(x);
    k_rankb<<<4, 1024>>>(s0, s1);
    k_seed<<<2, 1024>>>();
    k_kmeans<<<NBLK, 128>>>(idx_out, kw1, kb1, kw2, kb2, kw3, kb3,
                            bw1, bb1, bw2, bb2, bw3, bb3);
    k_wk<<<144, 128>>>(base);
    k_convg<<<MAXTILES, 256>>>(out);
}

// round 7
// speedup vs baseline: 1.4563x; 1.0636x over previous
#include <cuda_runtime.h>
#include <stdint.h>

#define BB 2
#define CC 32
#define HH 64
#define WW 64
#define PP 4096
#define FF 288
#define KK 32
#define NBB 32
#define HIDD 64
#define COUTT 64
#define NBLK 128      // persistent kmeans grid (64 blocks per batch)
#define MAXTILES 256
#define NSLOTS 48

// ---------------- device scratch (static, no allocation) ----------------
__device__ float    g_patches[BB*PP*FF];   // 9.4 MB
__device__ float    g_obs[BB*PP*CC];       // 1.0 MB
__device__ uint32_t g_rank[BB*2*PP];
__device__ int      g_permA[BB*PP];
__device__ int      g_initidx[BB*KK];
__device__ float    g_centers[BB*KK*CC];
__device__ float    g_part[NBLK][KK*CC + KK];   // per-block partials (no atomics)
__device__ float    g_shiftv[BB*KK];
__device__ int      g_cnt[BB*KK];
__device__ int      g_cursor[BB*KK];
__device__ int      g_off[BB*KK + 1];
__device__ int      g_plist[BB*PP];
__device__ int      g_tileBK[MAXTILES];
__device__ int      g_tileM0[MAXTILES];
__device__ int      g_ntiles;
__device__ float    g_attn[BB*KK*NBB];
__device__ float    g_biasv[BB*KK*COUTT];
__device__ float    g_wk[BB*KK*FF*COUTT];  // 4.7 MB
__device__ int      g_bslot[BB][NSLOTS];   // per-batch phase counters
__device__ int      g_gslot[4];            // global phase counters

// ---------------- Threefry-2x32 (JAX-compatible core) ----------------
__host__ __device__ inline void threefry2x32(uint32_t k0, uint32_t k1,
                                             uint32_t x0, uint32_t x1,
                                             uint32_t &o0, uint32_t &o1) {
    uint32_t ks2 = k0 ^ k1 ^ 0x1BD11BDAu;
    uint32_t v0 = x0 + k0, v1 = x1 + k1;
#define TF_R(r) { v0 += v1; v1 = (v1 << (r)) | (v1 >> (32 - (r))); v1 ^= v0; }
    TF_R(13) TF_R(15) TF_R(26) TF_R(6)   v0 += k1;  v1 += ks2 + 1u;
    TF_R(17) TF_R(29) TF_R(16) TF_R(24)  v0 += ks2; v1 += k0  + 2u;
    TF_R(13) TF_R(15) TF_R(26) TF_R(6)   v0 += k0;  v1 += k1  + 3u;
    TF_R(17) TF_R(29) TF_R(16) TF_R(24)  v0 += k1;  v1 += ks2 + 4u;
    TF_R(13) TF_R(15) TF_R(26) TF_R(6)   v0 += ks2; v1 += k0  + 5u;
#undef TF_R
    o0 = v0; o1 = v1;
}

// -------- slot-per-phase counter barrier (no reset races, no ABA) ----------
__device__ __forceinline__ void bar_wait(int* slot, int target) {
    __syncthreads();
    if (threadIdx.x == 0) {
        __threadfence();
        atomicAdd(slot, 1);
        while (*(volatile int*)slot < target) { }
        __threadfence();
    }
    __syncthreads();
}

// ---------------- unfold3 + channel-mean features (coalesced stores) ------
__global__ void k_prep(const float* __restrict__ x) {
    __shared__ float sbuf[4*FF];
    int warp = threadIdx.x >> 5, lane = threadIdx.x & 31;
    int gp = blockIdx.x * 4 + warp;           // 0..8191 = b*4096+p
    int b = gp >> 12, p = gp & 4095;
    int py = p >> 6, px = p & 63;
    const float* xc = x + (size_t)(b*CC + lane) * HH * WW;
    float* prow = sbuf + warp*FF + lane*9;
    float s = 0.f;
#pragma unroll
    for (int i = 0; i < 3; i++) {
        int yy = py + i - 1;
#pragma unroll
        for (int j = 0; j < 3; j++) {
            int xx = px + j - 1;
            float v = (yy >= 0 && yy < HH && xx >= 0 && xx < WW) ? xc[yy*WW + xx] : 0.f;
            prow[i*3 + j] = v;
            s += v;
        }
    }
    g_obs[(size_t)gp * CC + lane] = s / 9.f;
    __syncthreads();
    size_t base = (size_t)(blockIdx.x*4) * FF;
    for (int i = threadIdx.x; i < 4*FF; i += 128) g_patches[base + i] = sbuf[i];
}

// ---------------- bucket-based stable rank, keys fused in ------------------
__global__ void k_rankb(uint4 s0, uint4 s1) {
    int br = blockIdx.x;                 // 0..3 = b*2+r
    int b = br >> 1, r = br & 1;
    uint4 sk4 = b ? s1 : s0;
    uint32_t kk0 = r ? sk4.z : sk4.x;
    uint32_t kk1 = r ? sk4.w : sk4.y;
    __shared__ unsigned long long sorted[PP];   // 32 KB
    __shared__ int prefix[1025];
    __shared__ int cursor[1024];
    __shared__ int cnt[1024];
    __shared__ int wsum[32];
    int t = threadIdx.x;                 // 1024
    uint32_t kq[4];
#pragma unroll
    for (int q = 0; q < 4; q++) {
        uint32_t o0, o1;
        threefry2x32(kk0, kk1, 0u, (uint32_t)(t + q*1024), o0, o1);
        kq[q] = o0 ^ o1;
    }
    cnt[t] = 0;
    __syncthreads();
#pragma unroll
    for (int q = 0; q < 4; q++) atomicAdd(&cnt[kq[q] >> 22], 1);
    __syncthreads();
    int v = cnt[t];
    int lane = t & 31, wid = t >> 5;
    int s = v;
#pragma unroll
    for (int o = 1; o < 32; o <<= 1) { int u = __shfl_up_sync(0xffffffffu, s, o); if (lane >= o) s += u; }
    if (lane == 31) wsum[wid] = s;
    __syncthreads();
    if (wid == 0) {
        int ws = wsum[lane];
#pragma unroll
        for (int o = 1; o < 32; o <<= 1) { int u = __shfl_up_sync(0xffffffffu, ws, o); if (lane >= o) ws += u; }
        wsum[lane] = ws;
    }
    __syncthreads();
    int incl = s + (wid > 0 ? wsum[wid-1] : 0);
    prefix[t+1] = incl;
    if (t == 0) prefix[0] = 0;
    cursor[t] = incl - v;
    __syncthreads();
#pragma unroll
    for (int q = 0; q < 4; q++) {
        int p = atomicAdd(&cursor[kq[q] >> 22], 1);
        sorted[p] = ((unsigned long long)kq[q] << 32) | (uint32_t)(t + q*1024);
    }
    __syncthreads();
#pragma unroll
    for (int q = 0; q < 4; q++) {
        uint32_t key = kq[q];
        int i = t + q*1024;
        int bkt = key >> 22;
        int lo = prefix[bkt], hi = prefix[bkt+1];
        unsigned long long mine = ((unsigned long long)key << 32) | (uint32_t)i;
        int rr = lo;
        for (int j = lo; j < hi; j++) rr += (sorted[j] < mine) ? 1 : 0;
        g_rank[br*PP + i] = (uint32_t)rr;
    }
}

// ------- seed: global init + perm scatter + init-center gather (2 blocks) ---
__global__ void k_seed() {
    int b = blockIdx.x, t = threadIdx.x;   // 2 x 1024
    if (t < NSLOTS) g_bslot[b][t] = 0;
    if (b == 0 && t < 4) g_gslot[t] = 0;
    if (t < KK) { g_cnt[b*KK + t] = 0; g_cursor[b*KK + t] = 0; }
#pragma unroll
    for (int q = 0; q < 4; q++) {
        int i = t + q*1024;
        g_permA[b*PP + g_rank[(b*2)*PP + i]] = i;
    }
    __syncthreads();
#pragma unroll
    for (int q = 0; q < 4; q++) {
        int i = t + q*1024;
        uint32_t r1 = g_rank[(b*2+1)*PP + i];
        if (r1 < KK) g_initidx[b*KK + r1] = g_permA[b*PP + i];
    }
    __syncthreads();
    if (t < KK*CC) {
        int k = t >> 5, d = t & 31;
        g_centers[b*KK*CC + t] = g_obs[(size_t)(b*PP + g_initidx[b*KK + k])*CC + d];
    }
}

// --- persistent k-means + final assign + segmentation + sumsF + MLPs -------
__global__ void __launch_bounds__(128, 1) k_kmeans(
    float* idx_out,
    const float* __restrict__ kw1, const float* __restrict__ kb1,
    const float* __restrict__ kw2, const float* __restrict__ kb2,
    const float* __restrict__ kw3, const float* __restrict__ kb3,
    const float* __restrict__ bw1, const float* __restrict__ bb1,
    const float* __restrict__ bw2, const float* __restrict__ bb2,
    const float* __restrict__ bw3, const float* __restrict__ bb3)
{
    int bid = blockIdx.x;
    int b = bid >> 6;             // batch
    int sub = bid & 63;           // block within batch
    int t = threadIdx.x;          // 128
    int half = t & 1;
    int lp = t >> 1;              // local point 0..63
    int pi = sub*64 + lp;
    int lane = t & 31;
    int k0 = half * 16;
    __shared__ __align__(16) float sc[KK*CC];
    __shared__ __align__(16) float ssum[KK*CC];
    __shared__ float scn[KK];
    __shared__ float scnt[KK];
    __shared__ float s_cnt;
    __shared__ float s_sh;

    // point features in registers (persist across all iterations)
    float s[CC]; float sn = 0.f;
    {
        const float* op = g_obs + (size_t)(b*PP + pi) * CC;
#pragma unroll
        for (int d = 0; d < CC; d++) { s[d] = op[d]; sn += s[d]*s[d]; }
    }
    for (int i = t; i < KK*CC; i += 128) sc[i] = __ldcg(&g_centers[b*KK*CC + i]);
    __syncthreads();

    for (int it = 0; it < 20; it++) {
        int phase = it * 2;
        for (int i = t; i < KK*CC; i += 128) ssum[i] = 0.f;
        if (t < KK) {
            scnt[t] = 0.f;
            float q = 0.f;
#pragma unroll
            for (int d = 0; d < CC; d++) { float c = sc[t*CC + d]; q += c*c; }
            scn[t] = q;
        }
        __syncthreads();
        // ---- assign: 16 clusters per thread, pair-combined ----
        float best = 3.4028235e38f; int bi = 0;
        for (int k = k0; k < k0 + 16; k++) {
            float dot = 0.f;
#pragma unroll
            for (int d = 0; d < CC; d += 4) {
                float4 c4 = *(const float4*)&sc[k*CC + d];
                dot += s[d]*c4.x; dot += s[d+1]*c4.y;
                dot += s[d+2]*c4.z; dot += s[d+3]*c4.w;
            }
            float d2 = sn - 2.0f*dot + scn[k];
            if (d2 < best) { best = d2; bi = k; }
        }
        {
            float ob = __shfl_xor_sync(0xffffffffu, best, 1);
            int   ok = __shfl_xor_sync(0xffffffffu, bi, 1);
            if (ob < best || (ob == best && ok < bi)) { best = ob; bi = ok; }
        }
        // ---- counts via ballot (no per-point atomics) ----
#pragma unroll
        for (int k = 0; k < KK; k++) {
            unsigned m = __ballot_sync(0xffffffffu, bi == k);
            if (lane == k && m) atomicAdd(&scnt[k], (float)__popc(m) * 0.5f);
        }
        // ---- conflict-free rotated smem accumulation ----
#pragma unroll
        for (int i = 0; i < 16; i++) {
            int d = k0 + ((i + lp) & 15);
            atomicAdd(&ssum[bi*CC + d], s[d]);
        }
        __syncthreads();
        // ---- flush private partial (plain stores, no global atomics) ----
        for (int i = t; i < KK*CC; i += 128) g_part[bid][i] = ssum[i];
        if (t < KK) g_part[bid][KK*CC + t] = scnt[t];
        bar_wait(&g_bslot[b][phase], 64);
        // ---- reducers: block sub<32 owns cluster k=sub ----
        if (sub < KK) {
            if (t == 32) {
                float c = 0.f;
                for (int j = 0; j < 64; j++) c += __ldcg(&g_part[b*64 + j][KK*CC + sub]);
                s_cnt = c;
            }
            float acc = 0.f;
            if (t < 32) {
                int e = sub*CC + t;
                for (int j = 0; j < 64; j++) acc += __ldcg(&g_part[b*64 + j][e]);
            }
            __syncthreads();
            if (t < 32) {
                float oldc = sc[sub*CC + t];
                float cv = s_cnt;
                float nv = (cv > 0.f) ? (acc / fmaxf(cv, 1.f)) : oldc;
                float d = nv - oldc;
                float q = d*d;
#pragma unroll
                for (int o = 16; o > 0; o >>= 1) q += __shfl_xor_sync(0xffffffffu, q, o);
                g_centers[b*KK*CC + sub*CC + t] = nv;
                if (t == 0) g_shiftv[b*KK + sub] = sqrtf(q);
            }
        }
        bar_wait(&g_bslot[b][phase + 1], 64);
        // ---- reload centers + shift ----
        for (int i = t; i < KK*CC; i += 128) sc[i] = __ldcg(&g_centers[b*KK*CC + i]);
        if (t < KK) {
            float sv = __ldcg(&g_shiftv[b*KK + t]);
#pragma unroll
            for (int o = 16; o > 0; o >>= 1) sv += __shfl_xor_sync(0xffffffffu, sv, o);
            if (t == 0) s_sh = sv;
        }
        __syncthreads();
        if ((it + 1) >= 20 || s_sh < 20.48f) break;   // TOL*n = 0.005*4096
    }

    // ---- final assignment with converged centers ----
    if (t < KK) {
        float q = 0.f;
#pragma unroll
        for (int d = 0; d < CC; d++) { float c = sc[t*CC + d]; q += c*c; }
        scn[t] = q;
    }
    __syncthreads();
    float best = 3.4028235e38f; int bi = 0;
    for (int k = k0; k < k0 + 16; k++) {
        float dot = 0.f;
#pragma unroll
        for (int d = 0; d < CC; d += 4) {
            float4 c4 = *(const float4*)&sc[k*CC + d];
            dot += s[d]*c4.x; dot += s[d+1]*c4.y;
            dot += s[d+2]*c4.z; dot += s[d+3]*c4.w;
        }
        float d2 = sn - 2.0f*dot + scn[k];
        if (d2 < best) { best = d2; bi = k; }
    }
    {
        float ob = __shfl_xor_sync(0xffffffffu, best, 1);
        int   ok = __shfl_xor_sync(0xffffffffu, bi, 1);
        if (ob < best || (ob == best && ok < bi)) { best = ob; bi = ok; }
    }
    if (!half) {
        if (idx_out) idx_out[b*PP + pi] = (float)bi;
        atomicAdd(&g_cnt[b*KK + bi], 1);
    }
    bar_wait(&g_gslot[0], NBLK);
    // ---- offsets + tile list (single thread; tiny) ----
    if (bid == 0 && t == 0) {
        int off = 0, nt = 0;
        for (int bk = 0; bk < BB*KK; bk++) {
            g_off[bk] = off;
            int c = __ldcg(&g_cnt[bk]);
            for (int m = 0; m < c; m += 64) { g_tileBK[nt] = bk; g_tileM0[nt] = m; nt++; }
            off += c;
        }
        g_off[BB*KK] = off;
        g_ntiles = nt;
    }
    bar_wait(&g_gslot[1], NBLK);
    // ---- scatter pixel list ----
    if (!half) {
        int bk = b*KK + bi;
        int pos = __ldcg(&g_off[bk]) + atomicAdd(&g_cursor[bk], 1);
        g_plist[pos] = b*PP + pi;
    }
    bar_wait(&g_gslot[2], NBLK);
    // ---- per-cluster centroid + MLPs (blocks 0..63, one per bk) ----
    if (bid >= BB*KK) return;
    {
        int bk = bid;
        __shared__ float cen[FF];
        __shared__ float h1[HIDD];
        __shared__ float h2[HIDD];
        int lo = __ldcg(&g_off[bk]), hi = __ldcg(&g_off[bk+1]);
        float a0 = 0.f, a1 = 0.f, a2 = 0.f;
        for (int m = lo; m < hi; m++) {
            int gp = __ldcg(&g_plist[m]);
            const float* pr = g_patches + (size_t)gp*FF;
            a0 += __ldcg(&pr[t]); a1 += __ldcg(&pr[t+128]);
            if (t < 32) a2 += __ldcg(&pr[t+256]);
        }
        float dv = fmaxf((float)(hi - lo), 1.f);
        cen[t] = a0 / dv; cen[t+128] = a1 / dv;
        if (t < 32) cen[t+256] = a2 / dv;
        __syncthreads();
        if (t < HIDD) {
            float a = kb1[t];
            for (int f = 0; f < FF; f++) a += cen[f]*kw1[f*HIDD + t];
            h1[t] = fmaxf(a, 0.f);
        }
        __syncthreads();
        if (t < HIDD) {
            float a = kb2[t];
#pragma unroll
            for (int i = 0; i < HIDD; i++) a += h1[i]*kw2[i*HIDD + t];
            h2[t] = fmaxf(a, 0.f);
        }
        __syncthreads();
        if (t < NBB) {
            float a = kb3[t];
#pragma unroll
            for (int i = 0; i < HIDD; i++) a += h2[i]*kw3[i*NBB + t];
            float m = a;
#pragma unroll
            for (int off = 16; off > 0; off >>= 1) m = fmaxf(m, __shfl_xor_sync(0xffffffffu, m, off));
            float e = expf(a - m);
            float ss = e;
#pragma unroll
            for (int off = 16; off > 0; off >>= 1) ss += __shfl_xor_sync(0xffffffffu, ss, off);
            g_attn[bk*NBB + t] = e / ss;
        }
        __syncthreads();
        if (t < HIDD) {
            float a = bb1[t];
            for (int f = 0; f < FF; f++) a += cen[f]*bw1[f*HIDD + t];
            h1[t] = fmaxf(a, 0.f);
        }
        __syncthreads();
        if (t < HIDD) {
            float a = bb2[t];
#pragma unroll
            for (int i = 0; i < HIDD; i++) a += h1[i]*bw2[i*HIDD + t];
            h2[t] = fmaxf(a, 0.f);
        }
        __syncthreads();
        if (t < COUTT) {
            float a = bb3[t];
#pragma unroll
            for (int i = 0; i < HIDD; i++) a += h2[i]*bw3[i*COUTT + t];
            g_biasv[bk*COUTT + t] = a;
        }
    }
}

// ---------------- kernels = attn @ base_kernels ----------------
__global__ void k_wk(const float* __restrict__ base) {
    int col0 = blockIdx.x * 128;
    int t = threadIdx.x;             // 128
    __shared__ float bt[NBB*128];
    __shared__ float at[BB*KK*NBB];
#pragma unroll
    for (int n = 0; n < NBB; n++) bt[n*128 + t] = base[(size_t)n*(FF*COUTT) + col0 + t];
    for (int i = t; i < BB*KK*NBB; i += 128) at[i] = g_attn[i];
    __syncthreads();
    for (int row = 0; row < BB*KK; row++) {
        float acc = 0.f;
#pragma unroll
        for (int n = 0; n < NBB; n++) acc += at[row*NBB + n]*bt[n*128 + t];
        g_wk[(size_t)row*(FF*COUTT) + col0 + t] = acc;
    }
}

// ---------------- cluster-grouped GEMM conv ----------------
__global__ void k_convg(float* __restrict__ out) {
    __shared__ float As[64*36];
    __shared__ float Ws[32*64];
    __shared__ int sgp[64];
    int bid = blockIdx.x;
    if (bid >= g_ntiles) return;
    int bk = g_tileBK[bid], m0 = g_tileM0[bid];
    int lo = g_off[bk];
    int rows = g_off[bk+1] - lo - m0;
    if (rows > 64) rows = 64;
    int t = threadIdx.x;             // 256
    if (t < 64) sgp[t] = (t < rows) ? g_plist[lo + m0 + t] : -1;
    __syncthreads();
    int tx = t & 15, ty = t >> 4;
    float acc[4][4];
#pragma unroll
    for (int i = 0; i < 4; i++)
#pragma unroll
        for (int j = 0; j < 4; j++) acc[i][j] = 0.f;
    const float* wkbase = g_wk + (size_t)bk * (FF*COUTT);
    for (int kc = 0; kc < FF; kc += 32) {
#pragma unroll
        for (int u = 0; u < 2; u++) {
            int idx = t + u*256;
            int r = idx >> 3, c4 = idx & 7;
            int gp = sgp[r];
            float4 v = make_float4(0.f, 0.f, 0.f, 0.f);
            if (gp >= 0) v = *(const float4*)(g_patches + (size_t)gp*FF + kc + c4*4);
            *(float4*)(As + r*36 + c4*4) = v;
        }
#pragma unroll
        for (int u = 0; u < 2; u++) {
            int idx = t + u*256;
            int j = idx >> 4, c4 = idx & 15;
            *(float4*)(Ws + j*64 + c4*4) = *(const float4*)(wkbase + (size_t)(kc + j)*COUTT + c4*4);
        }
        __syncthreads();
#pragma unroll
        for (int j = 0; j < 32; j++) {
            float a0 = As[(ty*4+0)*36 + j];
            float a1 = As[(ty*4+1)*36 + j];
            float a2 = As[(ty*4+2)*36 + j];
            float a3 = As[(ty*4+3)*36 + j];
            float4 w = *(const float4*)(Ws + j*64 + tx*4);
            acc[0][0] += a0*w.x; acc[0][1] += a0*w.y; acc[0][2] += a0*w.z; acc[0][3] += a0*w.w;
            acc[1][0] += a1*w.x; acc[1][1] += a1*w.y; acc[1][2] += a1*w.z; acc[1][3] += a1*w.w;
            acc[2][0] += a2*w.x; acc[2][1] += a2*w.y; acc[2][2] += a2*w.z; acc[2][3] += a2*w.w;
            acc[3][0] += a3*w.x; acc[3][1] += a3*w.y; acc[3][2] += a3*w.z; acc[3][3] += a3*w.w;
        }
        __syncthreads();
    }
    int b = bk >> 5;
    float4 bias = *(const float4*)(g_biasv + bk*COUTT + tx*4);
#pragma unroll
    for (int i = 0; i < 4; i++) {
        int gp = sgp[ty*4 + i];
        if (gp < 0) continue;
        int p = gp & 4095;
        size_t ob = (size_t)(b*COUTT + tx*4) * PP + p;
        out[ob          ] = acc[i][0] + bias.x;
        out[ob +   PP   ] = acc[i][1] + bias.y;
        out[ob + 2*PP   ] = acc[i][2] + bias.z;
        out[ob + 3*PP   ] = acc[i][3] + bias.w;
    }
}

// ---------------- launch ----------------
extern "C" void kernel_launch(void* const* d_in, const int* in_sizes, int n_in,
                              void* d_out, int out_size) {
    const float* x    = (const float*)d_in[0];
    const float* base = (const float*)d_in[1];
    const float* kw1 = (const float*)d_in[2];  const float* kb1 = (const float*)d_in[3];
    const float* kw2 = (const float*)d_in[4];  const float* kb2 = (const float*)d_in[5];
    const float* kw3 = (const float*)d_in[6];  const float* kb3 = (const float*)d_in[7];
    const float* bw1 = (const float*)d_in[8];  const float* bb1 = (const float*)d_in[9];
    const float* bw2 = (const float*)d_in[10]; const float* bb2 = (const float*)d_in[11];
    const float* bw3 = (const float*)d_in[12]; const float* bb3 = (const float*)d_in[13];
    float* out = (float*)d_out;

    // JAX key chain (partitionable/fold-like split): key(42) = (0,42)
    uint32_t bk0x, bk0y, bk1x, bk1y;
    threefry2x32(0u, 42u, 0u, 0u, bk0x, bk0y);   // batch 0 key
    threefry2x32(0u, 42u, 0u, 1u, bk1x, bk1y);   // batch 1 key
    uint4 s0, s1;
    {
        uint32_t c0, c1, u, v;
        threefry2x32(bk0x, bk0y, 0u, 1u, u, v); s0.x = u; s0.y = v;
        threefry2x32(bk0x, bk0y, 0u, 0u, c0, c1);
        threefry2x32(c0, c1, 0u, 1u, u, v);     s0.z = u; s0.w = v;
        threefry2x32(bk1x, bk1y, 0u, 1u, u, v); s1.x = u; s1.y = v;
        threefry2x32(bk1x, bk1y, 0u, 0u, c0, c1);
        threefry2x32(c0, c1, 0u, 1u, u, v);     s1.z = u; s1.w = v;
    }

    float* idx_out = (out_size >= BB*COUTT*PP + BB*PP) ? (out + BB*COUTT*PP) : nullptr;

    k_prep<<<2048, 128>>>(x);
    k_rankb<<<4, 1024>>>(s0, s1);
    k_seed<<<2, 1024>>>();
    k_kmeans<<<NBLK, 128>>>(idx_out, kw1, kb1, kw2, kb2, kw3, kb3,
                            bw1, bb1, bw2, bb2, bw3, bb3);
    k_wk<<<144, 128>>>(base);
    k_convg<<<MAXTILES, 256>>>(out);
}

// round 8
// speedup vs baseline: 1.7478x; 1.2002x over previous
#include <cuda_runtime.h>
#include <stdint.h>

#define BB 2
#define CC 32
#define HH 64
#define WW 64
#define PP 4096
#define FF 288
#define KK 32
#define NBB 32
#define HIDD 64
#define COUTT 64
#define NBLK 128      // persistent kmeans grid (64 blocks per batch)
#define MAXTILES 256
#define NSLOTS 48

// ---------------- device scratch (static, no allocation) ----------------
__device__ float    g_patches[BB*PP*FF];   // 9.4 MB
__device__ float    g_obs[BB*PP*CC];       // 1.0 MB
__device__ uint32_t g_rank[BB*2*PP];
__device__ int      g_permA[BB*PP];
__device__ int      g_initidx[BB*KK];
__device__ float    g_centers[BB*KK*CC];
__device__ float    g_part[NBLK][KK*CC + KK];   // per-block partials (no atomics)
__device__ float    g_shiftv[BB*KK];
__device__ int      g_cnt[BB*KK];
__device__ int      g_cursor[BB*KK];
__device__ int      g_off[BB*KK + 1];
__device__ int      g_plist[BB*PP];
__device__ int      g_tileBK[MAXTILES];
__device__ int      g_tileM0[MAXTILES];
__device__ int      g_ntiles;
__device__ float    g_attn[BB*KK*NBB];
__device__ float    g_biasv[BB*KK*COUTT];
__device__ float    g_wk[BB*KK*FF*COUTT];  // 4.7 MB
__device__ int      g_bslot[BB][NSLOTS];   // per-batch phase counters
__device__ int      g_gslot[4];            // global phase counters

// ---------------- Threefry-2x32 (JAX-compatible core) ----------------
__host__ __device__ inline void threefry2x32(uint32_t k0, uint32_t k1,
                                             uint32_t x0, uint32_t x1,
                                             uint32_t &o0, uint32_t &o1) {
    uint32_t ks2 = k0 ^ k1 ^ 0x1BD11BDAu;
    uint32_t v0 = x0 + k0, v1 = x1 + k1;
#define TF_R(r) { v0 += v1; v1 = (v1 << (r)) | (v1 >> (32 - (r))); v1 ^= v0; }
    TF_R(13) TF_R(15) TF_R(26) TF_R(6)   v0 += k1;  v1 += ks2 + 1u;
    TF_R(17) TF_R(29) TF_R(16) TF_R(24)  v0 += ks2; v1 += k0  + 2u;
    TF_R(13) TF_R(15) TF_R(26) TF_R(6)   v0 += k0;  v1 += k1  + 3u;
    TF_R(17) TF_R(29) TF_R(16) TF_R(24)  v0 += k1;  v1 += ks2 + 4u;
    TF_R(13) TF_R(15) TF_R(26) TF_R(6)   v0 += ks2; v1 += k0  + 5u;
#undef TF_R
    o0 = v0; o1 = v1;
}

// -------- barrier primitives (slot-per-phase counters) ----------
__device__ __forceinline__ void bar_arrive(int* slot) {
    __syncthreads();
    if (threadIdx.x == 0) {
        __threadfence();
        atomicAdd(slot, 1);
    }
}
__device__ __forceinline__ void bar_spin(int* slot, int target) {
    if (threadIdx.x == 0) {
        while (*(volatile int*)slot < target) { }
        __threadfence();
    }
    __syncthreads();
}

// ---------------- unfold3 + channel-mean features (coalesced stores) ------
__global__ void k_prep(const float* __restrict__ x) {
    __shared__ float sbuf[4*FF];
    int warp = threadIdx.x >> 5, lane = threadIdx.x & 31;
    int gp = blockIdx.x * 4 + warp;           // 0..8191 = b*4096+p
    int b = gp >> 12, p = gp & 4095;
    int py = p >> 6, px = p & 63;
    const float* xc = x + (size_t)(b*CC + lane) * HH * WW;
    float* prow = sbuf + warp*FF + lane*9;
    float s = 0.f;
#pragma unroll
    for (int i = 0; i < 3; i++) {
        int yy = py + i - 1;
#pragma unroll
        for (int j = 0; j < 3; j++) {
            int xx = px + j - 1;
            float v = (yy >= 0 && yy < HH && xx >= 0 && xx < WW) ? xc[yy*WW + xx] : 0.f;
            prow[i*3 + j] = v;
            s += v;
        }
    }
    g_obs[(size_t)gp * CC + lane] = s / 9.f;
    __syncthreads();
    size_t base = (size_t)(blockIdx.x*4) * FF;
    for (int i = threadIdx.x; i < 4*FF; i += 128) g_patches[base + i] = sbuf[i];
}

// ---------------- bucket-based stable rank, keys fused in ------------------
__global__ void k_rankb(uint4 s0, uint4 s1) {
    int br = blockIdx.x;                 // 0..3 = b*2+r
    int b = br >> 1, r = br & 1;
    uint4 sk4 = b ? s1 : s0;
    uint32_t kk0 = r ? sk4.z : sk4.x;
    uint32_t kk1 = r ? sk4.w : sk4.y;
    __shared__ unsigned long long sorted[PP];   // 32 KB
    __shared__ int prefix[1025];
    __shared__ int cursor[1024];
    __shared__ int cnt[1024];
    __shared__ int wsum[32];
    int t = threadIdx.x;                 // 1024
    uint32_t kq[4];
#pragma unroll
    for (int q = 0; q < 4; q++) {
        uint32_t o0, o1;
        threefry2x32(kk0, kk1, 0u, (uint32_t)(t + q*1024), o0, o1);
        kq[q] = o0 ^ o1;
    }
    cnt[t] = 0;
    __syncthreads();
#pragma unroll
    for (int q = 0; q < 4; q++) atomicAdd(&cnt[kq[q] >> 22], 1);
    __syncthreads();
    int v = cnt[t];
    int lane = t & 31, wid = t >> 5;
    int s = v;
#pragma unroll
    for (int o = 1; o < 32; o <<= 1) { int u = __shfl_up_sync(0xffffffffu, s, o); if (lane >= o) s += u; }
    if (lane == 31) wsum[wid] = s;
    __syncthreads();
    if (wid == 0) {
        int ws = wsum[lane];
#pragma unroll
        for (int o = 1; o < 32; o <<= 1) { int u = __shfl_up_sync(0xffffffffu, ws, o); if (lane >= o) ws += u; }
        wsum[lane] = ws;
    }
    __syncthreads();
    int incl = s + (wid > 0 ? wsum[wid-1] : 0);
    prefix[t+1] = incl;
    if (t == 0) prefix[0] = 0;
    cursor[t] = incl - v;
    __syncthreads();
#pragma unroll
    for (int q = 0; q < 4; q++) {
        int p = atomicAdd(&cursor[kq[q] >> 22], 1);
        sorted[p] = ((unsigned long long)kq[q] << 32) | (uint32_t)(t + q*1024);
    }
    __syncthreads();
#pragma unroll
    for (int q = 0; q < 4; q++) {
        uint32_t key = kq[q];
        int i = t + q*1024;
        int bkt = key >> 22;
        int lo = prefix[bkt], hi = prefix[bkt+1];
        unsigned long long mine = ((unsigned long long)key << 32) | (uint32_t)i;
        int rr = lo;
        for (int j = lo; j < hi; j++) rr += (sorted[j] < mine) ? 1 : 0;
        g_rank[br*PP + i] = (uint32_t)rr;
    }
}

// ------- seed: global init + perm scatter + init-center gather (2 blocks) ---
__global__ void k_seed() {
    int b = blockIdx.x, t = threadIdx.x;   // 2 x 1024
    if (t < NSLOTS) g_bslot[b][t] = 0;
    if (b == 0 && t < 4) g_gslot[t] = 0;
    if (t < KK) { g_cnt[b*KK + t] = 0; g_cursor[b*KK + t] = 0; }
#pragma unroll
    for (int q = 0; q < 4; q++) {
        int i = t + q*1024;
        g_permA[b*PP + g_rank[(b*2)*PP + i]] = i;
    }
    __syncthreads();
#pragma unroll
    for (int q = 0; q < 4; q++) {
        int i = t + q*1024;
        uint32_t r1 = g_rank[(b*2+1)*PP + i];
        if (r1 < KK) g_initidx[b*KK + r1] = g_permA[b*PP + i];
    }
    __syncthreads();
    if (t < KK*CC) {
        int k = t >> 5, d = t & 31;
        g_centers[b*KK*CC + t] = g_obs[(size_t)(b*PP + g_initidx[b*KK + k])*CC + d];
    }
}

// --- persistent k-means + final assign + segmentation + sumsF + MLPs -------
__global__ void __launch_bounds__(128, 1) k_kmeans(
    float* idx_out,
    const float* __restrict__ kw1, const float* __restrict__ kb1,
    const float* __restrict__ kw2, const float* __restrict__ kb2,
    const float* __restrict__ kw3, const float* __restrict__ kb3,
    const float* __restrict__ bw1, const float* __restrict__ bb1,
    const float* __restrict__ bw2, const float* __restrict__ bb2,
    const float* __restrict__ bw3, const float* __restrict__ bb3)
{
    int bid = blockIdx.x;
    int b = bid >> 6;             // batch
    int sub = bid & 63;           // block within batch
    int t = threadIdx.x;          // 128
    int half = t & 1;
    int lp = t >> 1;              // local point 0..63
    int pi = sub*64 + lp;
    int lane = t & 31;
    int chunk = t >> 5;           // warp id 0..3
    int k0 = half * 16;
    __shared__ __align__(16) float sc[KK*CC];
    __shared__ __align__(16) float ssum[KK*CC];
    __shared__ float scn[KK];
    __shared__ float scnt[KK];
    __shared__ float sred[4][32];
    __shared__ float scred[64];
    __shared__ float s_sh;
    __shared__ int   soff[BB*KK + 1];

    // point features in registers (persist across all iterations)
    float s[CC]; float sn = 0.f;
    {
        const float* op = g_obs + (size_t)(b*PP + pi) * CC;
#pragma unroll
        for (int d = 0; d < CC; d++) { s[d] = op[d]; sn += s[d]*s[d]; }
    }
    for (int i = t; i < KK*CC; i += 128) sc[i] = __ldcg(&g_centers[b*KK*CC + i]);
    __syncthreads();

    for (int it = 0; it < 20; it++) {
        int phase = it * 2;
        for (int i = t; i < KK*CC; i += 128) ssum[i] = 0.f;
        if (t < KK) {
            scnt[t] = 0.f;
            float q = 0.f;
#pragma unroll
            for (int d = 0; d < CC; d++) { float c = sc[t*CC + d]; q += c*c; }
            scn[t] = q;
        }
        __syncthreads();
        // ---- assign: 16 clusters per thread, pair-combined ----
        float best = 3.4028235e38f; int bi = 0;
        for (int k = k0; k < k0 + 16; k++) {
            float dot = 0.f;
#pragma unroll
            for (int d = 0; d < CC; d += 4) {
                float4 c4 = *(const float4*)&sc[k*CC + d];
                dot += s[d]*c4.x; dot += s[d+1]*c4.y;
                dot += s[d+2]*c4.z; dot += s[d+3]*c4.w;
            }
            float d2 = sn - 2.0f*dot + scn[k];
            if (d2 < best) { best = d2; bi = k; }
        }
        {
            float ob = __shfl_xor_sync(0xffffffffu, best, 1);
            int   ok = __shfl_xor_sync(0xffffffffu, bi, 1);
            if (ob < best || (ob == best && ok < bi)) { best = ob; bi = ok; }
        }
        // ---- counts via ballot (no per-point atomics) ----
#pragma unroll
        for (int k = 0; k < KK; k++) {
            unsigned m = __ballot_sync(0xffffffffu, bi == k);
            if (lane == k && m) atomicAdd(&scnt[k], (float)__popc(m) * 0.5f);
        }
        // ---- conflict-free rotated smem accumulation ----
#pragma unroll
        for (int i = 0; i < 16; i++) {
            int d = k0 + ((i + lp) & 15);
            atomicAdd(&ssum[bi*CC + d], s[d]);
        }
        __syncthreads();
        // ---- flush private partial (plain stores, no global atomics) ----
        for (int i = t; i < KK*CC; i += 128) __stcg(&g_part[bid][i], ssum[i]);
        if (t < KK) __stcg(&g_part[bid][KK*CC + t], scnt[t]);
        bar_arrive(&g_bslot[b][phase]);
        // ---- reducers (sub<32): wait for all 64 partials, 4-way chunked ----
        if (sub < KK) {
            bar_spin(&g_bslot[b][phase], 64);
            float acc = 0.f;
            {
                int e = sub*CC + lane;
#pragma unroll
                for (int j = 0; j < 16; j++)
                    acc += __ldcg(&g_part[b*64 + chunk*16 + j][e]);
            }
            sred[chunk][lane] = acc;
            float cacc = (t < 64) ? __ldcg(&g_part[b*64 + t][KK*CC + sub]) : 0.f;
            scred[t & 63] = 0.f;   // harmless pre-touch
            __syncthreads();
            if (t < 64) scred[t] = cacc;
            __syncthreads();
            if (t < 32) {
                float tot = sred[0][t] + sred[1][t] + sred[2][t] + sred[3][t];
                float cv = 0.f;
                if (t < 16) { }   // count reduce below via lane ops
                // total count: reduce scred[0..63]
                float c2 = scred[t] + scred[t + 32];
#pragma unroll
                for (int o = 16; o > 0; o >>= 1) c2 += __shfl_xor_sync(0xffffffffu, c2, o);
                cv = c2;
                float oldc = sc[sub*CC + t];
                float nv = (cv > 0.f) ? (tot / fmaxf(cv, 1.f)) : oldc;
                float d = nv - oldc;
                float q = d*d;
#pragma unroll
                for (int o = 16; o > 0; o >>= 1) q += __shfl_xor_sync(0xffffffffu, q, o);
                __stcg(&g_centers[b*KK*CC + sub*CC + t], nv);
                if (t == 0) __stcg(&g_shiftv[b*KK + sub], sqrtf(q));
            }
            bar_arrive(&g_bslot[b][phase + 1]);
        }
        // ---- everyone: wait for 32 reducers, reload centers + shift ----
        bar_spin(&g_bslot[b][phase + 1], 32);
        for (int i = t; i < KK*CC; i += 128) sc[i] = __ldcg(&g_centers[b*KK*CC + i]);
        if (t < KK) {
            float sv = __ldcg(&g_shiftv[b*KK + t]);
#pragma unroll
            for (int o = 16; o > 0; o >>= 1) sv += __shfl_xor_sync(0xffffffffu, sv, o);
            if (t == 0) s_sh = sv;
        }
        __syncthreads();
        if ((it + 1) >= 20 || s_sh < 20.48f) break;   // TOL*n = 0.005*4096
    }

    // ---- final assignment with converged centers ----
    if (t < KK) {
        float q = 0.f;
#pragma unroll
        for (int d = 0; d < CC; d++) { float c = sc[t*CC + d]; q += c*c; }
        scn[t] = q;
    }
    __syncthreads();
    float best = 3.4028235e38f; int bi = 0;
    for (int k = k0; k < k0 + 16; k++) {
        float dot = 0.f;
#pragma unroll
        for (int d = 0; d < CC; d += 4) {
            float4 c4 = *(const float4*)&sc[k*CC + d];
            dot += s[d]*c4.x; dot += s[d+1]*c4.y;
            dot += s[d+2]*c4.z; dot += s[d+3]*c4.w;
        }
        float d2 = sn - 2.0f*dot + scn[k];
        if (d2 < best) { best = d2; bi = k; }
    }
    {
        float ob = __shfl_xor_sync(0xffffffffu, best, 1);
        int   ok = __shfl_xor_sync(0xffffffffu, bi, 1);
        if (ob < best || (ob == best && ok < bi)) { best = ob; bi = ok; }
    }
    if (!half) {
        if (idx_out) __stcg(&idx_out[b*PP + pi], (float)bi);
        atomicAdd(&g_cnt[b*KK + bi], 1);
    }
    bar_arrive(&g_gslot[0]);
    bar_spin(&g_gslot[0], NBLK);
    // ---- offsets: every block computes redundantly via smem scan ----
    {
        int c = 0, sc_ = 0;
        if (t < BB*KK) {
            c = __ldcg(&g_cnt[t]);
            sc_ = c;
#pragma unroll
            for (int o = 1; o < 32; o <<= 1) {
                int u = __shfl_up_sync(0xffffffffu, sc_, o);
                if (lane >= o) sc_ += u;
            }
        }
        __shared__ int w0tot;
        if (t == 31) w0tot = sc_;
        __syncthreads();
        if (t >= 32 && t < 64) sc_ += w0tot;
        if (t < BB*KK) soff[t + 1] = sc_;
        if (t == 0) soff[0] = 0;
        __syncthreads();
    }
    // block 0 publishes g_off + tile list (needed by k_convg)
    if (bid == 0) {
        if (t <= BB*KK) g_off[t] = soff[t];
        if (t == 0) {
            int nt = 0;
            for (int bk = 0; bk < BB*KK; bk++) {
                int c = soff[bk+1] - soff[bk];
                for (int m = 0; m < c; m += 64) { g_tileBK[nt] = bk; g_tileM0[nt] = m; nt++; }
            }
            g_ntiles = nt;
        }
    }
    // ---- scatter pixel list ----
    if (!half) {
        int bk = b*KK + bi;
        int pos = soff[bk] + atomicAdd(&g_cursor[bk], 1);
        __stcg(&g_plist[pos], b*PP + pi);
    }
    bar_arrive(&g_gslot[1]);
    bar_spin(&g_gslot[1], NBLK);
    // ---- per-cluster 288-dim partial sums: 2 blocks per cluster ----
    {
        int bk = bid & 63, h = bid >> 6;
        int lo = soff[bk], hi = soff[bk+1];
        float a0 = 0.f, a1 = 0.f, a2 = 0.f;
        for (int m = lo + h; m < hi; m += 2) {
            int gp = __ldcg(&g_plist[m]);
            const float* pr = g_patches + (size_t)gp*FF;
            a0 += __ldcg(&pr[t]); a1 += __ldcg(&pr[t+128]);
            if (t < 32) a2 += __ldcg(&pr[t+256]);
        }
        __stcg(&g_part[bid][t], a0);
        __stcg(&g_part[bid][t+128], a1);
        if (t < 32) __stcg(&g_part[bid][t+256], a2);
    }
    bar_arrive(&g_gslot[2]);
    if (bid >= BB*KK) return;
    bar_spin(&g_gslot[2], NBLK);
    // ---- combine + the two tiny MLPs + softmax (blocks 0..63) ----
    {
        int bk = bid;
        __shared__ float cen[FF];
        __shared__ float h1[HIDD];
        __shared__ float h2[HIDD];
        float dv = fmaxf((float)(soff[bk+1] - soff[bk]), 1.f);
        cen[t]     = (__ldcg(&g_part[bk][t])     + __ldcg(&g_part[bk+64][t]))     / dv;
        cen[t+128] = (__ldcg(&g_part[bk][t+128]) + __ldcg(&g_part[bk+64][t+128])) / dv;
        if (t < 32)
            cen[t+256] = (__ldcg(&g_part[bk][t+256]) + __ldcg(&g_part[bk+64][t+256])) / dv;
        __syncthreads();
        if (t < HIDD) {
            float a = kb1[t];
            for (int f = 0; f < FF; f++) a += cen[f]*kw1[f*HIDD + t];
            h1[t] = fmaxf(a, 0.f);
        }
        __syncthreads();
        if (t < HIDD) {
            float a = kb2[t];
#pragma unroll
            for (int i = 0; i < HIDD; i++) a += h1[i]*kw2[i*HIDD + t];
            h2[t] = fmaxf(a, 0.f);
        }
        __syncthreads();
        if (t < NBB) {
            float a = kb3[t];
#pragma unroll
            for (int i = 0; i < HIDD; i++) a += h2[i]*kw3[i*NBB + t];
            float m = a;
#pragma unroll
            for (int off = 16; off > 0; off >>= 1) m = fmaxf(m, __shfl_xor_sync(0xffffffffu, m, off));
            float e = expf(a - m);
            float ss = e;
#pragma unroll
            for (int off = 16; off > 0; off >>= 1) ss += __shfl_xor_sync(0xffffffffu, ss, off);
            g_attn[bk*NBB + t] = e / ss;
        }
        __syncthreads();
        if (t < HIDD) {
            float a = bb1[t];
            for (int f = 0; f < FF; f++) a += cen[f]*bw1[f*HIDD + t];
            h1[t] = fmaxf(a, 0.f);
        }
        __syncthreads();
        if (t < HIDD) {
            float a = bb2[t];
#pragma unroll
            for (int i = 0; i < HIDD; i++) a += h1[i]*bw2[i*HIDD + t];
            h2[t] = fmaxf(a, 0.f);
        }
        __syncthreads();
        if (t < COUTT) {
            float a = bb3[t];
#pragma unroll
            for (int i = 0; i < HIDD; i++) a += h2[i]*bw3[i*COUTT + t];
            g_biasv[bk*COUTT + t] = a;
        }
    }
}

// ---------------- kernels = attn @ base_kernels ----------------
__global__ void k_wk(const float* __restrict__ base) {
    int col0 = blockIdx.x * 128;
    int t = threadIdx.x;             // 128
    __shared__ float bt[NBB*128];
    __shared__ float at[BB*KK*NBB];
#pragma unroll
    for (int n = 0; n < NBB; n++) bt[n*128 + t] = base[(size_t)n*(FF*COUTT) + col0 + t];
    for (int i = t; i < BB*KK*NBB; i += 128) at[i] = g_attn[i];
    __syncthreads();
    for (int row = 0; row < BB*KK; row++) {
        float acc = 0.f;
#pragma unroll
        for (int n = 0; n < NBB; n++) acc += at[row*NBB + n]*bt[n*128 + t];
        g_wk[(size_t)row*(FF*COUTT) + col0 + t] = acc;
    }
}

// ---------------- cluster-grouped GEMM conv ----------------
__global__ void k_convg(float* __restrict__ out) {
    __shared__ float As[64*36];
    __shared__ float Ws[32*64];
    __shared__ int sgp[64];
    int bid = blockIdx.x;
    if (bid >= g_ntiles) return;
    int bk = g_tileBK[bid], m0 = g_tileM0[bid];
    int lo = g_off[bk];
    int rows = g_off[bk+1] - lo - m0;
    if (rows > 64) rows = 64;
    int t = threadIdx.x;             // 256
    if (t < 64) sgp[t] = (t < rows) ? g_plist[lo + m0 + t] : -1;
    __syncthreads();
    int tx = t & 15, ty = t >> 4;
    float acc[4][4];
#pragma unroll
    for (int i = 0; i < 4; i++)
#pragma unroll
        for (int j = 0; j < 4; j++) acc[i][j] = 0.f;
    const float* wkbase = g_wk + (size_t)bk * (FF*COUTT);
    for (int kc = 0; kc < FF; kc += 32) {
#pragma unroll
        for (int u = 0; u < 2; u++) {
            int idx = t + u*256;
            int r = idx >> 3, c4 = idx & 7;
            int gp = sgp[r];
            float4 v = make_float4(0.f, 0.f, 0.f, 0.f);
            if (gp >= 0) v = *(const float4*)(g_patches + (size_t)gp*FF + kc + c4*4);
            *(float4*)(As + r*36 + c4*4) = v;
        }
#pragma unroll
        for (int u = 0; u < 2; u++) {
            int idx = t + u*256;
            int j = idx >> 4, c4 = idx & 15;
            *(float4*)(Ws + j*64 + c4*4) = *(const float4*)(wkbase + (size_t)(kc + j)*COUTT + c4*4);
        }
        __syncthreads();
#pragma unroll
        for (int j = 0; j < 32; j++) {
            float a0 = As[(ty*4+0)*36 + j];
            float a1 = As[(ty*4+1)*36 + j];
            float a2 = As[(ty*4+2)*36 + j];
            float a3 = As[(ty*4+3)*36 + j];
            float4 w = *(const float4*)(Ws + j*64 + tx*4);
            acc[0][0] += a0*w.x; acc[0][1] += a0*w.y; acc[0][2] += a0*w.z; acc[0][3] += a0*w.w;
            acc[1][0] += a1*w.x; acc[1][1] += a1*w.y; acc[1][2] += a1*w.z; acc[1][3] += a1*w.w;
            acc[2][0] += a2*w.x; acc[2][1] += a2*w.y; acc[2][2] += a2*w.z; acc[2][3] += a2*w.w;
            acc[3][0] += a3*w.x; acc[3][1] += a3*w.y; acc[3][2] += a3*w.z; acc[3][3] += a3*w.w;
        }
        __syncthreads();
    }
    int b = bk >> 5;
    float4 bias = *(const float4*)(g_biasv + bk*COUTT + tx*4);
#pragma unroll
    for (int i = 0; i < 4; i++) {
        int gp = sgp[ty*4 + i];
        if (gp < 0) continue;
        int p = gp & 4095;
        size_t ob = (size_t)(b*COUTT + tx*4) * PP + p;
        out[ob          ] = acc[i][0] + bias.x;
        out[ob +   PP   ] = acc[i][1] + bias.y;
        out[ob + 2*PP   ] = acc[i][2] + bias.z;
        out[ob + 3*PP   ] = acc[i][3] + bias.w;
    }
}

// ---------------- launch ----------------
extern "C" void kernel_launch(void* const* d_in, const int* in_sizes, int n_in,
                              void* d_out, int out_size) {
    const float* x    = (const float*)d_in[0];
    const float* base = (const float*)d_in[1];
    const float* kw1 = (const float*)d_in[2];  const float* kb1 = (const float*)d_in[3];
    const float* kw2 = (const float*)d_in[4];  const float* kb2 = (const float*)d_in[5];
    const float* kw3 = (const float*)d_in[6];  const float* kb3 = (const float*)d_in[7];
    const float* bw1 = (const float*)d_in[8];  const float* bb1 = (const float*)d_in[9];
    const float* bw2 = (const float*)d_in[10]; const float* bb2 = (const float*)d_in[11];
    const float* bw3 = (const float*)d_in[12]; const float* bb3 = (const float*)d_in[13];
    float* out = (float*)d_out;

    // JAX key chain (partitionable/fold-like split): key(42) = (0,42)
    uint32_t bk0x, bk0y, bk1x, bk1y;
    threefry2x32(0u, 42u, 0u, 0u, bk0x, bk0y);   // batch 0 key
    threefry2x32(0u, 42u, 0u, 1u, bk1x, bk1y);   // batch 1 key
    uint4 s0, s1;
    {
        uint32_t c0, c1, u, v;
        threefry2x32(bk0x, bk0y, 0u, 1u, u, v); s0.x = u; s0.y = v;
        threefry2x32(bk0x, bk0y, 0u, 0u, c0, c1);
        threefry2x32(c0, c1, 0u, 1u, u, v);     s0.z = u; s0.w = v;
        threefry2x32(bk1x, bk1y, 0u, 1u, u, v); s1.x = u; s1.y = v;
        threefry2x32(bk1x, bk1y, 0u, 0u, c0, c1);
        threefry2x32(c0, c1, 0u, 1u, u, v);     s1.z = u; s1.w = v;
    }

    float* idx_out = (out_size >= BB*COUTT*PP + BB*PP) ? (out + BB*COUTT*PP) : nullptr;

    k_prep<<<2048, 128>>>(x);
    k_rankb<<<4, 1024>>>(s0, s1);
    k_seed<<<2, 1024>>>();
    k_kmeans<<<NBLK, 128>>>(idx_out, kw1, kb1, kw2, kb2, kw3, kb3,
                            bw1, bb1, bw2, bb2, bw3, bb3);
    k_wk<<<144, 128>>>(base);
    k_convg<<<MAXTILES, 256>>>(out);
}

// round 9
// speedup vs baseline: 1.8197x; 1.0411x over previous
#include <cuda_runtime.h>
#include <stdint.h>

#define BB 2
#define CC 32
#define HH 64
#define WW 64
#define PP 4096
#define FF 288
#define KK 32
#define NBB 32
#define HIDD 64
#define COUTT 64
#define NBLK 128      // persistent kmeans grid (64 blocks per batch)
#define MAXTILES 256
#define NSLOTS 48

// ---------------- device scratch (static, no allocation) ----------------
__device__ float    g_patches[BB*PP*FF];   // 9.4 MB
__device__ float    g_obs[BB*PP*CC];       // 1.0 MB
__device__ uint32_t g_rank[BB*2*PP];
__device__ int      g_permA[BB*PP];
__device__ int      g_initidx[BB*KK];
__device__ float    g_centers[BB*KK*CC];
__device__ float    g_part[NBLK][KK*CC + KK];   // per-block partials (no atomics)
__device__ float    g_shiftv[BB*KK];
__device__ int      g_cnt[BB*KK];
__device__ int      g_cursor[BB*KK];
__device__ int      g_off[BB*KK + 1];
__device__ int      g_plist[BB*PP];
__device__ int      g_tileBK[MAXTILES];
__device__ int      g_tileM0[MAXTILES];
__device__ int      g_ntiles;
__device__ float    g_attn[BB*KK*NBB];
__device__ float    g_biasv[BB*KK*COUTT];
__device__ float    g_wk[BB*KK*FF*COUTT];  // 4.7 MB
__device__ int      g_bslot[BB][NSLOTS];   // per-batch phase counters
__device__ int      g_gslot[4];            // global phase counters

// ---------------- Threefry-2x32 (JAX-compatible core) ----------------
__host__ __device__ inline void threefry2x32(uint32_t k0, uint32_t k1,
                                             uint32_t x0, uint32_t x1,
                                             uint32_t &o0, uint32_t &o1) {
    uint32_t ks2 = k0 ^ k1 ^ 0x1BD11BDAu;
    uint32_t v0 = x0 + k0, v1 = x1 + k1;
#define TF_R(r) { v0 += v1; v1 = (v1 << (r)) | (v1 >> (32 - (r))); v1 ^= v0; }
    TF_R(13) TF_R(15) TF_R(26) TF_R(6)   v0 += k1;  v1 += ks2 + 1u;
    TF_R(17) TF_R(29) TF_R(16) TF_R(24)  v0 += ks2; v1 += k0  + 2u;
    TF_R(13) TF_R(15) TF_R(26) TF_R(6)   v0 += k0;  v1 += k1  + 3u;
    TF_R(17) TF_R(29) TF_R(16) TF_R(24)  v0 += k1;  v1 += ks2 + 4u;
    TF_R(13) TF_R(15) TF_R(26) TF_R(6)   v0 += ks2; v1 += k0  + 5u;
#undef TF_R
    o0 = v0; o1 = v1;
}

// -------- barrier primitives: release-increment / acquire-poll ------------
// No __threadfence (gpu-scope MEMBAR + L1 flush). The release RED publishes
// all prior stores; the acquire LD orders all subsequent loads.
__device__ __forceinline__ void bar_arrive(int* slot) {
    __syncthreads();
    if (threadIdx.x == 0) {
        asm volatile("red.release.gpu.global.add.s32 [%0], 1;"
                     :: "l"(slot) : "memory");
    }
}
__device__ __forceinline__ void bar_spin(int* slot, int target) {
    if (threadIdx.x == 0) {
        int v;
        do {
            asm volatile("ld.acquire.gpu.global.s32 %0, [%1];"
                         : "=r"(v) : "l"(slot) : "memory");
        } while (v < target);
    }
    __syncthreads();
}

// ---------------- unfold3 + channel-mean features (coalesced stores) ------
__global__ void k_prep(const float* __restrict__ x) {
    __shared__ float sbuf[4*FF];
    int warp = threadIdx.x >> 5, lane = threadIdx.x & 31;
    int gp = blockIdx.x * 4 + warp;           // 0..8191 = b*4096+p
    int b = gp >> 12, p = gp & 4095;
    int py = p >> 6, px = p & 63;
    const float* xc = x + (size_t)(b*CC + lane) * HH * WW;
    float* prow = sbuf + warp*FF + lane*9;
    float s = 0.f;
#pragma unroll
    for (int i = 0; i < 3; i++) {
        int yy = py + i - 1;
#pragma unroll
        for (int j = 0; j < 3; j++) {
            int xx = px + j - 1;
            float v = (yy >= 0 && yy < HH && xx >= 0 && xx < WW) ? xc[yy*WW + xx] : 0.f;
            prow[i*3 + j] = v;
            s += v;
        }
    }
    g_obs[(size_t)gp * CC + lane] = s / 9.f;
    __syncthreads();
    size_t base = (size_t)(blockIdx.x*4) * FF;
    for (int i = threadIdx.x; i < 4*FF; i += 128) g_patches[base + i] = sbuf[i];
}

// ---------------- bucket-based stable rank, keys fused in ------------------
__global__ void k_rankb(uint4 s0, uint4 s1) {
    int br = blockIdx.x;                 // 0..3 = b*2+r
    int b = br >> 1, r = br & 1;
    uint4 sk4 = b ? s1 : s0;
    uint32_t kk0 = r ? sk4.z : sk4.x;
    uint32_t kk1 = r ? sk4.w : sk4.y;
    __shared__ unsigned long long sorted[PP];   // 32 KB
    __shared__ int prefix[1025];
    __shared__ int cursor[1024];
    __shared__ int cnt[1024];
    __shared__ int wsum[32];
    int t = threadIdx.x;                 // 1024
    uint32_t kq[4];
#pragma unroll
    for (int q = 0; q < 4; q++) {
        uint32_t o0, o1;
        threefry2x32(kk0, kk1, 0u, (uint32_t)(t + q*1024), o0, o1);
        kq[q] = o0 ^ o1;
    }
    cnt[t] = 0;
    __syncthreads();
#pragma unroll
    for (int q = 0; q < 4; q++) atomicAdd(&cnt[kq[q] >> 22], 1);
    __syncthreads();
    int v = cnt[t];
    int lane = t & 31, wid = t >> 5;
    int s = v;
#pragma unroll
    for (int o = 1; o < 32; o <<= 1) { int u = __shfl_up_sync(0xffffffffu, s, o); if (lane >= o) s += u; }
    if (lane == 31) wsum[wid] = s;
    __syncthreads();
    if (wid == 0) {
        int ws = wsum[lane];
#pragma unroll
        for (int o = 1; o < 32; o <<= 1) { int u = __shfl_up_sync(0xffffffffu, ws, o); if (lane >= o) ws += u; }
        wsum[lane] = ws;
    }
    __syncthreads();
    int incl = s + (wid > 0 ? wsum[wid-1] : 0);
    prefix[t+1] = incl;
    if (t == 0) prefix[0] = 0;
    cursor[t] = incl - v;
    __syncthreads();
#pragma unroll
    for (int q = 0; q < 4; q++) {
        int p = atomicAdd(&cursor[kq[q] >> 22], 1);
        sorted[p] = ((unsigned long long)kq[q] << 32) | (uint32_t)(t + q*1024);
    }
    __syncthreads();
#pragma unroll
    for (int q = 0; q < 4; q++) {
        uint32_t key = kq[q];
        int i = t + q*1024;
        int bkt = key >> 22;
        int lo = prefix[bkt], hi = prefix[bkt+1];
        unsigned long long mine = ((unsigned long long)key << 32) | (uint32_t)i;
        int rr = lo;
        for (int j = lo; j < hi; j++) rr += (sorted[j] < mine) ? 1 : 0;
        g_rank[br*PP + i] = (uint32_t)rr;
    }
}

// ------- seed: global init + perm scatter + init-center gather (2 blocks) ---
__global__ void k_seed() {
    int b = blockIdx.x, t = threadIdx.x;   // 2 x 1024
    if (t < NSLOTS) g_bslot[b][t] = 0;
    if (b == 0 && t < 4) g_gslot[t] = 0;
    if (t < KK) { g_cnt[b*KK + t] = 0; g_cursor[b*KK + t] = 0; }
#pragma unroll
    for (int q = 0; q < 4; q++) {
        int i = t + q*1024;
        g_permA[b*PP + g_rank[(b*2)*PP + i]] = i;
    }
    __syncthreads();
#pragma unroll
    for (int q = 0; q < 4; q++) {
        int i = t + q*1024;
        uint32_t r1 = g_rank[(b*2+1)*PP + i];
        if (r1 < KK) g_initidx[b*KK + r1] = g_permA[b*PP + i];
    }
    __syncthreads();
    if (t < KK*CC) {
        int k = t >> 5, d = t & 31;
        g_centers[b*KK*CC + t] = g_obs[(size_t)(b*PP + g_initidx[b*KK + k])*CC + d];
    }
}

// --- persistent k-means + final assign + segmentation + sumsF + MLPs -------
__global__ void __launch_bounds__(128, 1) k_kmeans(
    float* idx_out,
    const float* __restrict__ kw1, const float* __restrict__ kb1,
    const float* __restrict__ kw2, const float* __restrict__ kb2,
    const float* __restrict__ kw3, const float* __restrict__ kb3,
    const float* __restrict__ bw1, const float* __restrict__ bb1,
    const float* __restrict__ bw2, const float* __restrict__ bb2,
    const float* __restrict__ bw3, const float* __restrict__ bb3)
{
    int bid = blockIdx.x;
    int b = bid >> 6;             // batch
    int sub = bid & 63;           // block within batch
    int t = threadIdx.x;          // 128
    int half = t & 1;
    int lp = t >> 1;              // local point 0..63
    int pi = sub*64 + lp;
    int lane = t & 31;
    int chunk = t >> 5;           // warp id 0..3
    int k0 = half * 16;
    __shared__ __align__(16) float sc[KK*CC];
    __shared__ __align__(16) float ssum[KK*CC];
    __shared__ float scn[KK];
    __shared__ float scnt[KK];
    __shared__ float sred[4][32];
    __shared__ float scred[64];
    __shared__ float s_sh;
    __shared__ int   soff[BB*KK + 1];

    // point features in registers (persist across all iterations)
    float s[CC]; float sn = 0.f;
    {
        const float* op = g_obs + (size_t)(b*PP + pi) * CC;
#pragma unroll
        for (int d = 0; d < CC; d++) { s[d] = op[d]; sn += s[d]*s[d]; }
    }
    for (int i = t; i < KK*CC; i += 128) sc[i] = __ldcg(&g_centers[b*KK*CC + i]);
    __syncthreads();

    for (int it = 0; it < 20; it++) {
        int phase = it * 2;
        for (int i = t; i < KK*CC; i += 128) ssum[i] = 0.f;
        if (t < KK) {
            scnt[t] = 0.f;
            float q = 0.f;
#pragma unroll
            for (int d = 0; d < CC; d++) { float c = sc[t*CC + d]; q += c*c; }
            scn[t] = q;
        }
        __syncthreads();
        // ---- assign: 16 clusters per thread, pair-combined ----
        float best = 3.4028235e38f; int bi = 0;
        for (int k = k0; k < k0 + 16; k++) {
            float dot = 0.f;
#pragma unroll
            for (int d = 0; d < CC; d += 4) {
                float4 c4 = *(const float4*)&sc[k*CC + d];
                dot += s[d]*c4.x; dot += s[d+1]*c4.y;
                dot += s[d+2]*c4.z; dot += s[d+3]*c4.w;
            }
            float d2 = sn - 2.0f*dot + scn[k];
            if (d2 < best) { best = d2; bi = k; }
        }
        {
            float ob = __shfl_xor_sync(0xffffffffu, best, 1);
            int   ok = __shfl_xor_sync(0xffffffffu, bi, 1);
            if (ob < best || (ob == best && ok < bi)) { best = ob; bi = ok; }
        }
        // ---- counts via ballot (no per-point atomics) ----
#pragma unroll
        for (int k = 0; k < KK; k++) {
            unsigned m = __ballot_sync(0xffffffffu, bi == k);
            if (lane == k && m) atomicAdd(&scnt[k], (float)__popc(m) * 0.5f);
        }
        // ---- conflict-free rotated smem accumulation ----
#pragma unroll
        for (int i = 0; i < 16; i++) {
            int d = k0 + ((i + lp) & 15);
            atomicAdd(&ssum[bi*CC + d], s[d]);
        }
        __syncthreads();
        // ---- flush private partial (plain stores, no global atomics) ----
        for (int i = t; i < KK*CC; i += 128) __stcg(&g_part[bid][i], ssum[i]);
        if (t < KK) __stcg(&g_part[bid][KK*CC + t], scnt[t]);
        bar_arrive(&g_bslot[b][phase]);
        // ---- reducers (sub<32): wait for all 64 partials, 4-way chunked ----
        if (sub < KK) {
            bar_spin(&g_bslot[b][phase], 64);
            float acc = 0.f;
            {
                int e = sub*CC + lane;
#pragma unroll
                for (int j = 0; j < 16; j++)
                    acc += __ldcg(&g_part[b*64 + chunk*16 + j][e]);
            }
            sred[chunk][lane] = acc;
            float cacc = (t < 64) ? __ldcg(&g_part[b*64 + t][KK*CC + sub]) : 0.f;
            __syncthreads();
            if (t < 64) scred[t] = cacc;
            __syncthreads();
            if (t < 32) {
                float tot = sred[0][t] + sred[1][t] + sred[2][t] + sred[3][t];
                // total count: reduce scred[0..63]
                float c2 = scred[t] + scred[t + 32];
#pragma unroll
                for (int o = 16; o > 0; o >>= 1) c2 += __shfl_xor_sync(0xffffffffu, c2, o);
                float cv = c2;
                float oldc = sc[sub*CC + t];
                float nv = (cv > 0.f) ? (tot / fmaxf(cv, 1.f)) : oldc;
                float d = nv - oldc;
                float q = d*d;
#pragma unroll
                for (int o = 16; o > 0; o >>= 1) q += __shfl_xor_sync(0xffffffffu, q, o);
                __stcg(&g_centers[b*KK*CC + sub*CC + t], nv);
                if (t == 0) __stcg(&g_shiftv[b*KK + sub], sqrtf(q));
            }
            bar_arrive(&g_bslot[b][phase + 1]);
        }
        // ---- everyone: wait for 32 reducers, reload centers + shift ----
        bar_spin(&g_bslot[b][phase + 1], 32);
        for (int i = t; i < KK*CC; i += 128) sc[i] = __ldcg(&g_centers[b*KK*CC + i]);
        if (t < KK) {
            float sv = __ldcg(&g_shiftv[b*KK + t]);
#pragma unroll
            for (int o = 16; o > 0; o >>= 1) sv += __shfl_xor_sync(0xffffffffu, sv, o);
            if (t == 0) s_sh = sv;
        }
        __syncthreads();
        if ((it + 1) >= 20 || s_sh < 20.48f) break;   // TOL*n = 0.005*4096
    }

    // ---- final assignment with converged centers ----
    if (t < KK) {
        float q = 0.f;
#pragma unroll
        for (int d = 0; d < CC; d++) { float c = sc[t*CC + d]; q += c*c; }
        scn[t] = q;
    }
    __syncthreads();
    float best = 3.4028235e38f; int bi = 0;
    for (int k = k0; k < k0 + 16; k++) {
        float dot = 0.f;
#pragma unroll
        for (int d = 0; d < CC; d += 4) {
            float4 c4 = *(const float4*)&sc[k*CC + d];
            dot += s[d]*c4.x; dot += s[d+1]*c4.y;
            dot += s[d+2]*c4.z; dot += s[d+3]*c4.w;
        }
        float d2 = sn - 2.0f*dot + scn[k];
        if (d2 < best) { best = d2; bi = k; }
    }
    {
        float ob = __shfl_xor_sync(0xffffffffu, best, 1);
        int   ok = __shfl_xor_sync(0xffffffffu, bi, 1);
        if (ob < best || (ob == best && ok < bi)) { best = ob; bi = ok; }
    }
    if (!half) {
        if (idx_out) __stcg(&idx_out[b*PP + pi], (float)bi);
        atomicAdd(&g_cnt[b*KK + bi], 1);
    }
    bar_arrive(&g_gslot[0]);
    bar_spin(&g_gslot[0], NBLK);
    // ---- offsets: every block computes redundantly via smem scan ----
    {
        int c = 0, sc_ = 0;
        if (t < BB*KK) {
            c = __ldcg(&g_cnt[t]);
            sc_ = c;
#pragma unroll
            for (int o = 1; o < 32; o <<= 1) {
                int u = __shfl_up_sync(0xffffffffu, sc_, o);
                if (lane >= o) sc_ += u;
            }
        }
        __shared__ int w0tot;
        if (t == 31) w0tot = sc_;
        __syncthreads();
        if (t >= 32 && t < 64) sc_ += w0tot;
        if (t < BB*KK) soff[t + 1] = sc_;
        if (t == 0) soff[0] = 0;
        __syncthreads();
    }
    // block 0 publishes g_off + tile list (needed by k_convg)
    if (bid == 0) {
        if (t <= BB*KK) g_off[t] = soff[t];
        if (t == 0) {
            int nt = 0;
            for (int bk = 0; bk < BB*KK; bk++) {
                int c = soff[bk+1] - soff[bk];
                for (int m = 0; m < c; m += 64) { g_tileBK[nt] = bk; g_tileM0[nt] = m; nt++; }
            }
            g_ntiles = nt;
        }
    }
    // ---- scatter pixel list ----
    if (!half) {
        int bk = b*KK + bi;
        int pos = soff[bk] + atomicAdd(&g_cursor[bk], 1);
        __stcg(&g_plist[pos], b*PP + pi);
    }
    bar_arrive(&g_gslot[1]);
    bar_spin(&g_gslot[1], NBLK);
    // ---- per-cluster 288-dim partial sums: 2 blocks per cluster ----
    {
        int bk = bid & 63, h = bid >> 6;
        int lo = soff[bk], hi = soff[bk+1];
        float a0 = 0.f, a1 = 0.f, a2 = 0.f;
        for (int m = lo + h; m < hi; m += 2) {
            int gp = __ldcg(&g_plist[m]);
            const float* pr = g_patches + (size_t)gp*FF;
            a0 += __ldcg(&pr[t]); a1 += __ldcg(&pr[t+128]);
            if (t < 32) a2 += __ldcg(&pr[t+256]);
        }
        __stcg(&g_part[bid][t], a0);
        __stcg(&g_part[bid][t+128], a1);
        if (t < 32) __stcg(&g_part[bid][t+256], a2);
    }
    bar_arrive(&g_gslot[2]);
    if (bid >= BB*KK) return;
    bar_spin(&g_gslot[2], NBLK);
    // ---- combine + the two tiny MLPs + softmax (blocks 0..63) ----
    {
        int bk = bid;
        __shared__ float cen[FF];
        __shared__ float h1[HIDD];
        __shared__ float h2[HIDD];
        float dv = fmaxf((float)(soff[bk+1] - soff[bk]), 1.f);
        cen[t]     = (__ldcg(&g_part[bk][t])     + __ldcg(&g_part[bk+64][t]))     / dv;
        cen[t+128] = (__ldcg(&g_part[bk][t+128]) + __ldcg(&g_part[bk+64][t+128])) / dv;
        if (t < 32)
            cen[t+256] = (__ldcg(&g_part[bk][t+256]) + __ldcg(&g_part[bk+64][t+256])) / dv;
        __syncthreads();
        if (t < HIDD) {
            float a = kb1[t];
            for (int f = 0; f < FF; f++) a += cen[f]*kw1[f*HIDD + t];
            h1[t] = fmaxf(a, 0.f);
        }
        __syncthreads();
        if (t < HIDD) {
            float a = kb2[t];
#pragma unroll
            for (int i = 0; i < HIDD; i++) a += h1[i]*kw2[i*HIDD + t];
            h2[t] = fmaxf(a, 0.f);
        }
        __syncthreads();
        if (t < NBB) {
            float a = kb3[t];
#pragma unroll
            for (int i = 0; i < HIDD; i++) a += h2[i]*kw3[i*NBB + t];
            float m = a;
#pragma unroll
            for (int off = 16; off > 0; off >>= 1) m = fmaxf(m, __shfl_xor_sync(0xffffffffu, m, off));
            float e = expf(a - m);
            float ss = e;
#pragma unroll
            for (int off = 16; off > 0; off >>= 1) ss += __shfl_xor_sync(0xffffffffu, ss, off);
            g_attn[bk*NBB + t] = e / ss;
        }
        __syncthreads();
        if (t < HIDD) {
            float a = bb1[t];
            for (int f = 0; f < FF; f++) a += cen[f]*bw1[f*HIDD + t];
            h1[t] = fmaxf(a, 0.f);
        }
        __syncthreads();
        if (t < HIDD) {
            float a = bb2[t];
#pragma unroll
            for (int i = 0; i < HIDD; i++) a += h1[i]*bw2[i*HIDD + t];
            h2[t] = fmaxf(a, 0.f);
        }
        __syncthreads();
        if (t < COUTT) {
            float a = bb3[t];
#pragma unroll
            for (int i = 0; i < HIDD; i++) a += h2[i]*bw3[i*COUTT + t];
            g_biasv[bk*COUTT + t] = a;
        }
    }
}

// ---------------- kernels = attn @ base_kernels ----------------
__global__ void k_wk(const float* __restrict__ base) {
    int col0 = blockIdx.x * 128;
    int t = threadIdx.x;             // 128
    __shared__ float bt[NBB*128];
    __shared__ float at[BB*KK*NBB];
#pragma unroll
    for (int n = 0; n < NBB; n++) bt[n*128 + t] = base[(size_t)n*(FF*COUTT) + col0 + t];
    for (int i = t; i < BB*KK*NBB; i += 128) at[i] = g_attn[i];
    __syncthreads();
    for (int row = 0; row < BB*KK; row++) {
        float acc = 0.f;
#pragma unroll
        for (int n = 0; n < NBB; n++) acc += at[row*NBB + n]*bt[n*128 + t];
        g_wk[(size_t)row*(FF*COUTT) + col0 + t] = acc;
    }
}

// ---------------- cluster-grouped GEMM conv ----------------
__global__ void k_convg(float* __restrict__ out) {
    __shared__ float As[64*36];
    __shared__ float Ws[32*64];
    __shared__ int sgp[64];
    int bid = blockIdx.x;
    if (bid >= g_ntiles) return;
    int bk = g_tileBK[bid], m0 = g_tileM0[bid];
    int lo = g_off[bk];
    int rows = g_off[bk+1] - lo - m0;
    if (rows > 64) rows = 64;
    int t = threadIdx.x;             // 256
    if (t < 64) sgp[t] = (t < rows) ? g_plist[lo + m0 + t] : -1;
    __syncthreads();
    int tx = t & 15, ty = t >> 4;
    float acc[4][4];
#pragma unroll
    for (int i = 0; i < 4; i++)
#pragma unroll
        for (int j = 0; j < 4; j++) acc[i][j] = 0.f;
    const float* wkbase = g_wk + (size_t)bk * (FF*COUTT);
    for (int kc = 0; kc < FF; kc += 32) {
#pragma unroll
        for (int u = 0; u < 2; u++) {
            int idx = t + u*256;
            int r = idx >> 3, c4 = idx & 7;
            int gp = sgp[r];
            float4 v = make_float4(0.f, 0.f, 0.f, 0.f);
            if (gp >= 0) v = *(const float4*)(g_patches + (size_t)gp*FF + kc + c4*4);
            *(float4*)(As + r*36 + c4*4) = v;
        }
#pragma unroll
        for (int u = 0; u < 2; u++) {
            int idx = t + u*256;
            int j = idx >> 4, c4 = idx & 15;
            *(float4*)(Ws + j*64 + c4*4) = *(const float4*)(wkbase + (size_t)(kc + j)*COUTT + c4*4);
        }
        __syncthreads();
#pragma unroll
        for (int j = 0; j < 32; j++) {
            float a0 = As[(ty*4+0)*36 + j];
            float a1 = As[(ty*4+1)*36 + j];
            float a2 = As[(ty*4+2)*36 + j];
            float a3 = As[(ty*4+3)*36 + j];
            float4 w = *(const float4*)(Ws + j*64 + tx*4);
            acc[0][0] += a0*w.x; acc[0][1] += a0*w.y; acc[0][2] += a0*w.z; acc[0][3] += a0*w.w;
            acc[1][0] += a1*w.x; acc[1][1] += a1*w.y; acc[1][2] += a1*w.z; acc[1][3] += a1*w.w;
            acc[2][0] += a2*w.x; acc[2][1] += a2*w.y; acc[2][2] += a2*w.z; acc[2][3] += a2*w.w;
            acc[3][0] += a3*w.x; acc[3][1] += a3*w.y; acc[3][2] += a3*w.z; acc[3][3] += a3*w.w;
        }
        __syncthreads();
    }
    int b = bk >> 5;
    float4 bias = *(const float4*)(g_biasv + bk*COUTT + tx*4);
#pragma unroll
    for (int i = 0; i < 4; i++) {
        int gp = sgp[ty*4 + i];
        if (gp < 0) continue;
        int p = gp & 4095;
        size_t ob = (size_t)(b*COUTT + tx*4) * PP + p;
        out[ob          ] = acc[i][0] + bias.x;
        out[ob +   PP   ] = acc[i][1] + bias.y;
        out[ob + 2*PP   ] = acc[i][2] + bias.z;
        out[ob + 3*PP   ] = acc[i][3] + bias.w;
    }
}

// ---------------- launch ----------------
extern "C" void kernel_launch(void* const* d_in, const int* in_sizes, int n_in,
                              void* d_out, int out_size) {
    const float* x    = (const float*)d_in[0];
    const float* base = (const float*)d_in[1];
    const float* kw1 = (const float*)d_in[2];  const float* kb1 = (const float*)d_in[3];
    const float* kw2 = (const float*)d_in[4];  const float* kb2 = (const float*)d_in[5];
    const float* kw3 = (const float*)d_in[6];  const float* kb3 = (const float*)d_in[7];
    const float* bw1 = (const float*)d_in[8];  const float* bb1 = (const float*)d_in[9];
    const float* bw2 = (const float*)d_in[10]; const float* bb2 = (const float*)d_in[11];
    const float* bw3 = (const float*)d_in[12]; const float* bb3 = (const float*)d_in[13];
    float* out = (float*)d_out;

    // JAX key chain (partitionable/fold-like split): key(42) = (0,42)
    uint32_t bk0x, bk0y, bk1x, bk1y;
    threefry2x32(0u, 42u, 0u, 0u, bk0x, bk0y);   // batch 0 key
    threefry2x32(0u, 42u, 0u, 1u, bk1x, bk1y);   // batch 1 key
    uint4 s0, s1;
    {
        uint32_t c0, c1, u, v;
        threefry2x32(bk0x, bk0y, 0u, 1u, u, v); s0.x = u; s0.y = v;
        threefry2x32(bk0x, bk0y, 0u, 0u, c0, c1);
        threefry2x32(c0, c1, 0u, 1u, u, v);     s0.z = u; s0.w = v;
        threefry2x32(bk1x, bk1y, 0u, 1u, u, v); s1.x = u; s1.y = v;
        threefry2x32(bk1x, bk1y, 0u, 0u, c0, c1);
        threefry2x32(c0, c1, 0u, 1u, u, v);     s1.z = u; s1.w = v;
    }

    float* idx_out = (out_size >= BB*COUTT*PP + BB*PP) ? (out + BB*COUTT*PP) : nullptr;

    k_prep<<<2048, 128>>>(x);
    k_rankb<<<4, 1024>>>(s0, s1);
    k_seed<<<2, 1024>>>();
    k_kmeans<<<NBLK, 128>>>(idx_out, kw1, kb1, kw2, kb2, kw3, kb3,
                            bw1, bb1, bw2, bb2, bw3, bb3);
    k_wk<<<144, 128>>>(base);
    k_convg<<<MAXTILES, 256>>>(out);
}